// round 3
// baseline (speedup 1.0000x reference)
#include <cuda_runtime.h>
#include <cstdint>

// ---------------------------------------------------------------------------
// PatternCWanRoPE: fused interleaved RoPE + causal attention
//   q,k,v : (B=2, S=2048, H=16, D=128) fp32     freqs : (1, S, 1, D)
//   out   : (B, H, S, D) fp32
// Strategy (R2): RoPE+transpose+tf32 prologue -> scratch (B,H,S,D);
// FA2 flash attention with mma.sync.m16n8k8.tf32 (fallback HMMA),
// BM=BN=64, 4 warps/CTA, online softmax in exp2 space.
// ---------------------------------------------------------------------------

#define B_ 2
#define S_ 2048
#define H_ 16
#define D_ 128
#define BH_ (B_ * H_)

#define BM 64
#define BN 64
#define NTHREADS 128

#define KSTRIDE 132   // 132 % 32 == 4 -> conflict-free (g*stride + t4)
#define VSTRIDE 136   // 136 % 32 == 8 -> conflict-free (t4*stride + g)
#define PSTRIDE 68    // 68  % 32 == 4

#define SMEM_FLOATS (BN * KSTRIDE + BN * VSTRIDE + BM * PSTRIDE)
#define SMEM_BYTES  (SMEM_FLOATS * 4)

// Scratch: rope'd Q (pre-scaled by 1/sqrt(D)*log2(e)), rope'd K, V — all
// tf32-rounded fp32 in (B,H,S,D) layout. Static device globals (no alloc).
__device__ float g_q[(size_t)BH_ * S_ * D_];
__device__ float g_k[(size_t)BH_ * S_ * D_];
__device__ float g_v[(size_t)BH_ * S_ * D_];

__device__ __forceinline__ float to_tf32(float x) {
    uint32_t u;
    asm("cvt.rna.tf32.f32 %0, %1;" : "=r"(u) : "f"(x));
    return __uint_as_float(u);
}

__device__ __forceinline__ float fast_exp2(float x) {
    float y;
    asm("ex2.approx.f32 %0, %1;" : "=f"(y) : "f"(x));
    return y;
}

__device__ __forceinline__ void mma_tf32(float c[4], const uint32_t a[4],
                                         uint32_t b0, uint32_t b1) {
    asm volatile(
        "mma.sync.aligned.m16n8k8.row.col.f32.tf32.tf32.f32 "
        "{%0,%1,%2,%3}, {%4,%5,%6,%7}, {%8,%9}, {%0,%1,%2,%3};\n"
        : "+f"(c[0]), "+f"(c[1]), "+f"(c[2]), "+f"(c[3])
        : "r"(a[0]), "r"(a[1]), "r"(a[2]), "r"(a[3]), "r"(b0), "r"(b1));
}

// ---------------------------------------------------------------------------
// Prologue: RoPE(q,k), copy v; transpose (B,S,H,D)->(B,H,S,D); tf32-round.
// One thread per interleaved pair. 4,194,304 threads.
// ---------------------------------------------------------------------------
__global__ void rope_prep_kernel(const float* __restrict__ q,
                                 const float* __restrict__ k,
                                 const float* __restrict__ v,
                                 const float* __restrict__ freqs) {
    int pid = blockIdx.x * blockDim.x + threadIdx.x;
    const int TOTAL = B_ * S_ * H_ * (D_ / 2);
    if (pid >= TOTAL) return;

    int dp = pid & 63;               // D/2 = 64 pairs
    int h  = (pid >> 6) & (H_ - 1);
    int s  = (pid >> 10) & (S_ - 1);
    int b  = pid >> 21;

    size_t in_off  = ((((size_t)b * S_ + s) * H_ + h) * D_) + 2 * dp;
    size_t f_off   = (size_t)s * D_ + 2 * dp;
    size_t out_off = ((((size_t)b * H_ + h) * S_ + s) * D_) + 2 * dp;

    float2 f  = *(const float2*)(freqs + f_off);
    float2 xq = *(const float2*)(q + in_off);
    float2 xk = *(const float2*)(k + in_off);
    float2 xv = *(const float2*)(v + in_off);

    // 1/sqrt(128) * log2(e): fold softmax scale + exp2 conversion into Q.
    const float QS = 0.08838834764831845f * 1.4426950408889634f;

    float2 oq, ok, ov;
    oq.x = to_tf32((f.x * xq.x - f.y * xq.y) * QS);
    oq.y = to_tf32((f.y * xq.x + f.x * xq.y) * QS);
    ok.x = to_tf32(f.x * xk.x - f.y * xk.y);
    ok.y = to_tf32(f.y * xk.x + f.x * xk.y);
    ov.x = to_tf32(xv.x);
    ov.y = to_tf32(xv.y);

    *(float2*)(g_q + out_off) = oq;
    *(float2*)(g_k + out_off) = ok;
    *(float2*)(g_v + out_off) = ov;
}

// ---------------------------------------------------------------------------
// Flash attention: one CTA per (bh, 64-row q tile). 4 warps; warp w owns
// q rows [16w, 16w+16). m16n8k8 tf32 mma for QK^T and PV.
// ---------------------------------------------------------------------------
__global__ void __launch_bounds__(NTHREADS, 2)
attn_kernel(float* __restrict__ out) {
    extern __shared__ float smem[];
    float* Ks = smem;                       // [BN][KSTRIDE]
    float* Vs = smem + BN * KSTRIDE;        // [BN][VSTRIDE]
    float* Ps = Vs + BN * VSTRIDE;          // [BM][PSTRIDE]

    const int bh = blockIdx.x;
    const int qt = (gridDim.y - 1) - blockIdx.y;  // big tiles scheduled first
    const int m0 = qt * BM;
    const int tid  = threadIdx.x;
    const int warp = tid >> 5;
    const int lane = tid & 31;
    const int g  = lane >> 2;   // groupID
    const int t4 = lane & 3;    // threadID_in_group

    const float* Qg = g_q + (size_t)bh * S_ * D_;
    const float* Kg = g_k + (size_t)bh * S_ * D_;
    const float* Vg = g_v + (size_t)bh * S_ * D_;

    // ---- Stage Q tile through Ks (coalesced), then into register frags ----
#pragma unroll
    for (int i = 0; i < 16; i++) {
        int idx = tid + i * 128;        // float4 slot 0..2047
        int row = idx >> 5;
        int c4  = idx & 31;
        float4 val = *(const float4*)(Qg + (size_t)(m0 + row) * D_ + c4 * 4);
        *(float4*)(Ks + row * KSTRIDE + c4 * 4) = val;
    }
    __syncthreads();

    const int rl0 = warp * 16 + g;      // local q row (also rl0+8)
    uint32_t qa[16][4];
#pragma unroll
    for (int kf = 0; kf < 16; kf++) {
        qa[kf][0] = __float_as_uint(Ks[rl0 * KSTRIDE + kf * 8 + t4]);
        qa[kf][1] = __float_as_uint(Ks[(rl0 + 8) * KSTRIDE + kf * 8 + t4]);
        qa[kf][2] = __float_as_uint(Ks[rl0 * KSTRIDE + kf * 8 + t4 + 4]);
        qa[kf][3] = __float_as_uint(Ks[(rl0 + 8) * KSTRIDE + kf * 8 + t4 + 4]);
    }

    float oacc[16][4];
#pragma unroll
    for (int i = 0; i < 16; i++) {
        oacc[i][0] = 0.f; oacc[i][1] = 0.f; oacc[i][2] = 0.f; oacc[i][3] = 0.f;
    }
    float mrow0 = -1e30f, mrow1 = -1e30f;
    float lrow0 = 0.f,    lrow1 = 0.f;

    const int ntiles = qt + 1;
    for (int t = 0; t < ntiles; t++) {
        const int n0 = t * BN;
        __syncthreads();   // previous tile's consumers done (incl. Q staging)

        // ---- Load K,V tiles (coalesced float4) ----
#pragma unroll
        for (int i = 0; i < 16; i++) {
            int idx = tid + i * 128;
            int row = idx >> 5;
            int c4  = idx & 31;
            float4 kv = *(const float4*)(Kg + (size_t)(n0 + row) * D_ + c4 * 4);
            *(float4*)(Ks + row * KSTRIDE + c4 * 4) = kv;
            float4 vv = *(const float4*)(Vg + (size_t)(n0 + row) * D_ + c4 * 4);
            *(float4*)(Vs + row * VSTRIDE + c4 * 4) = vv;
        }
        __syncthreads();

        // ---- S = Q K^T (16x64 per warp) ----
        float sacc[8][4];
#pragma unroll
        for (int i = 0; i < 8; i++) {
            sacc[i][0] = 0.f; sacc[i][1] = 0.f; sacc[i][2] = 0.f; sacc[i][3] = 0.f;
        }
#pragma unroll
        for (int kf = 0; kf < 16; kf++) {
#pragma unroll
            for (int nf = 0; nf < 8; nf++) {
                uint32_t b0 = __float_as_uint(Ks[(nf * 8 + g) * KSTRIDE + kf * 8 + t4]);
                uint32_t b1 = __float_as_uint(Ks[(nf * 8 + g) * KSTRIDE + kf * 8 + t4 + 4]);
                mma_tf32(sacc[nf], qa[kf], b0, b1);
            }
        }

        // ---- Causal mask (diagonal tile only) ----
        if (n0 == m0) {
#pragma unroll
            for (int nf = 0; nf < 8; nf++) {
                int c0 = nf * 8 + 2 * t4;
                if (c0     > rl0)     sacc[nf][0] = -1e30f;
                if (c0 + 1 > rl0)     sacc[nf][1] = -1e30f;
                if (c0     > rl0 + 8) sacc[nf][2] = -1e30f;
                if (c0 + 1 > rl0 + 8) sacc[nf][3] = -1e30f;
            }
        }

        // ---- Online softmax (scores already in log2 space) ----
        float tm0 = -1e30f, tm1 = -1e30f;
#pragma unroll
        for (int nf = 0; nf < 8; nf++) {
            tm0 = fmaxf(tm0, fmaxf(sacc[nf][0], sacc[nf][1]));
            tm1 = fmaxf(tm1, fmaxf(sacc[nf][2], sacc[nf][3]));
        }
        tm0 = fmaxf(tm0, __shfl_xor_sync(0xffffffffu, tm0, 1));
        tm0 = fmaxf(tm0, __shfl_xor_sync(0xffffffffu, tm0, 2));
        tm1 = fmaxf(tm1, __shfl_xor_sync(0xffffffffu, tm1, 1));
        tm1 = fmaxf(tm1, __shfl_xor_sync(0xffffffffu, tm1, 2));

        float mn0 = fmaxf(mrow0, tm0);
        float mn1 = fmaxf(mrow1, tm1);
        float alpha0 = fast_exp2(mrow0 - mn0);
        float alpha1 = fast_exp2(mrow1 - mn1);
        mrow0 = mn0; mrow1 = mn1;

        float rs0 = 0.f, rs1 = 0.f;
#pragma unroll
        for (int nf = 0; nf < 8; nf++) {
            sacc[nf][0] = fast_exp2(sacc[nf][0] - mn0);
            sacc[nf][1] = fast_exp2(sacc[nf][1] - mn0);
            sacc[nf][2] = fast_exp2(sacc[nf][2] - mn1);
            sacc[nf][3] = fast_exp2(sacc[nf][3] - mn1);
            rs0 += sacc[nf][0] + sacc[nf][1];
            rs1 += sacc[nf][2] + sacc[nf][3];
        }
        rs0 += __shfl_xor_sync(0xffffffffu, rs0, 1);
        rs0 += __shfl_xor_sync(0xffffffffu, rs0, 2);
        rs1 += __shfl_xor_sync(0xffffffffu, rs1, 1);
        rs1 += __shfl_xor_sync(0xffffffffu, rs1, 2);
        lrow0 = lrow0 * alpha0 + rs0;
        lrow1 = lrow1 * alpha1 + rs1;

#pragma unroll
        for (int nf = 0; nf < 16; nf++) {
            oacc[nf][0] *= alpha0; oacc[nf][1] *= alpha0;
            oacc[nf][2] *= alpha1; oacc[nf][3] *= alpha1;
        }

        // ---- P -> shared (warp-private rows), reload as A frags ----
#pragma unroll
        for (int nf = 0; nf < 8; nf++) {
            *(float2*)(Ps + rl0 * PSTRIDE + nf * 8 + 2 * t4) =
                make_float2(sacc[nf][0], sacc[nf][1]);
            *(float2*)(Ps + (rl0 + 8) * PSTRIDE + nf * 8 + 2 * t4) =
                make_float2(sacc[nf][2], sacc[nf][3]);
        }
        __syncwarp();

        // ---- O += P V (16x128 per warp) ----
#pragma unroll
        for (int kf = 0; kf < 8; kf++) {
            uint32_t a[4];
            a[0] = __float_as_uint(Ps[rl0 * PSTRIDE + kf * 8 + t4]);
            a[1] = __float_as_uint(Ps[(rl0 + 8) * PSTRIDE + kf * 8 + t4]);
            a[2] = __float_as_uint(Ps[rl0 * PSTRIDE + kf * 8 + t4 + 4]);
            a[3] = __float_as_uint(Ps[(rl0 + 8) * PSTRIDE + kf * 8 + t4 + 4]);
#pragma unroll
            for (int nf = 0; nf < 16; nf++) {
                uint32_t b0 = __float_as_uint(Vs[(kf * 8 + t4) * VSTRIDE + nf * 8 + g]);
                uint32_t b1 = __float_as_uint(Vs[(kf * 8 + t4 + 4) * VSTRIDE + nf * 8 + g]);
                mma_tf32(oacc[nf], a, b0, b1);
            }
        }
    }

    // ---- Epilogue: normalize and store (B,H,S,D); 32B-sector aligned ----
    float inv0 = 1.0f / lrow0;
    float inv1 = 1.0f / lrow1;
    float* o0 = out + ((size_t)bh * S_ + (m0 + rl0)) * D_;
    float* o1 = out + ((size_t)bh * S_ + (m0 + rl0 + 8)) * D_;
#pragma unroll
    for (int nf = 0; nf < 16; nf++) {
        int c = nf * 8 + 2 * t4;
        *(float2*)(o0 + c) = make_float2(oacc[nf][0] * inv0, oacc[nf][1] * inv0);
        *(float2*)(o1 + c) = make_float2(oacc[nf][2] * inv1, oacc[nf][3] * inv1);
    }
}

// ---------------------------------------------------------------------------
extern "C" void kernel_launch(void* const* d_in, const int* in_sizes, int n_in,
                              void* d_out, int out_size) {
    const float* q     = (const float*)d_in[0];
    const float* k     = (const float*)d_in[1];
    const float* v     = (const float*)d_in[2];
    const float* freqs = (const float*)d_in[3];
    float* out = (float*)d_out;

    (void)in_sizes; (void)n_in; (void)out_size;

    // idempotent; legal during graph capture (not a stream op)
    cudaFuncSetAttribute(attn_kernel,
                         cudaFuncAttributeMaxDynamicSharedMemorySize,
                         SMEM_BYTES);

    const int TOTAL_PAIRS = B_ * S_ * H_ * (D_ / 2);
    rope_prep_kernel<<<TOTAL_PAIRS / 256, 256>>>(q, k, v, freqs);

    dim3 grid(BH_, S_ / BM);
    attn_kernel<<<grid, NTHREADS, SMEM_BYTES>>>(out);
}

// round 5
// speedup vs baseline: 1.8358x; 1.8358x over previous
#include <cuda_runtime.h>
#include <cuda_fp16.h>
#include <cstdint>

// ---------------------------------------------------------------------------
// PatternCWanRoPE R5: fp16 warp-MMA flash attention (m16n8k16) + ldmatrix.
//   q,k,v : (B=2, S=2048, H=16, D=128) fp32   freqs : (1,S,1,D)
//   out   : (B,H,S,D) fp32
// Prologue: RoPE(q,k) (+softmax scale & log2e folded into q), fp16 convert,
//           (B,S,H,D)->(B,H,S,D) transpose. V converted/transposed likewise
//           but stays row-major [s][d] (PV uses ldmatrix.trans).
// Attention: BM=BN=64, 4 warps/CTA, online exp2 softmax, fp32 accumulators.
// All SMEM fragment traffic via ldmatrix.x4 on a 272B-pitch layout
// (17 x 16B chunks/row -> conflict-free for every access pattern here).
// ---------------------------------------------------------------------------

#define B_ 2
#define S_ 2048
#define H_ 16
#define D_ 128
#define BH_ 32

#define BM 64
#define BN 64
#define NTHREADS 128

#define KPITCH_B 272          // 136 halves/row (128 data + 8 pad)
#define PPITCH_B 144          // 72 halves/row (64 data + 8 pad)
#define OFF_K 0
#define OFF_V (64 * KPITCH_B)             // 17408
#define OFF_P (2 * 64 * KPITCH_B)         // 34816
#define SMEM_BYTES (OFF_P + 64 * PPITCH_B) // 44032

// fp16 scratch in (B,H,S,D): rope'd Q (pre-scaled by 1/sqrt(D)*log2e),
// rope'd K, V.
__device__ __half g_q[(size_t)BH_ * S_ * D_];
__device__ __half g_k[(size_t)BH_ * S_ * D_];
__device__ __half g_v[(size_t)BH_ * S_ * D_];

// ---------------------------------------------------------------------------
__device__ __forceinline__ uint32_t smem_u32(const void* p) {
    uint32_t a;
    asm("{ .reg .u64 t; cvta.to.shared.u64 t, %1; cvt.u32.u64 %0, t; }"
        : "=r"(a) : "l"(p));
    return a;
}
__device__ __forceinline__ float fast_exp2(float x) {
    float y; asm("ex2.approx.f32 %0, %1;" : "=f"(y) : "f"(x));
    return y;
}
__device__ __forceinline__ void ldsm_x4(uint32_t r[4], uint32_t a) {
    asm volatile("ldmatrix.sync.aligned.m8n8.x4.shared.b16 {%0,%1,%2,%3}, [%4];"
                 : "=r"(r[0]), "=r"(r[1]), "=r"(r[2]), "=r"(r[3]) : "r"(a));
}
__device__ __forceinline__ void ldsm_x4_t(uint32_t r[4], uint32_t a) {
    asm volatile("ldmatrix.sync.aligned.m8n8.x4.trans.shared.b16 {%0,%1,%2,%3}, [%4];"
                 : "=r"(r[0]), "=r"(r[1]), "=r"(r[2]), "=r"(r[3]) : "r"(a));
}
__device__ __forceinline__ void mma_f16(float c[4], const uint32_t a[4],
                                        uint32_t b0, uint32_t b1) {
    asm volatile(
        "mma.sync.aligned.m16n8k16.row.col.f32.f16.f16.f32 "
        "{%0,%1,%2,%3}, {%4,%5,%6,%7}, {%8,%9}, {%0,%1,%2,%3};\n"
        : "+f"(c[0]), "+f"(c[1]), "+f"(c[2]), "+f"(c[3])
        : "r"(a[0]), "r"(a[1]), "r"(a[2]), "r"(a[3]), "r"(b0), "r"(b1));
}

// ---------------------------------------------------------------------------
// Prologue: RoPE(q,k) + scale, fp16 convert, transpose to (B,H,S,D). V too.
// ---------------------------------------------------------------------------
__global__ void rope_prep_kernel(const float* __restrict__ q,
                                 const float* __restrict__ k,
                                 const float* __restrict__ v,
                                 const float* __restrict__ freqs) {
    int pid = blockIdx.x * blockDim.x + threadIdx.x;
    int dp = pid & 63;
    int h  = (pid >> 6) & (H_ - 1);
    int s  = (pid >> 10) & (S_ - 1);
    int b  = pid >> 21;

    size_t in_off  = ((((size_t)b * S_ + s) * H_ + h) * D_) + 2 * dp;
    size_t f_off   = (size_t)s * D_ + 2 * dp;
    size_t out_off = ((((size_t)b * H_ + h) * S_ + s) * D_) + 2 * dp;

    float2 f  = *(const float2*)(freqs + f_off);
    float2 xq = *(const float2*)(q + in_off);
    float2 xk = *(const float2*)(k + in_off);
    float2 xv = *(const float2*)(v + in_off);

    const float QS = 0.08838834764831845f * 1.4426950408889634f; // 1/sqrt(D)*log2e

    *(half2*)(g_q + out_off) = __floats2half2_rn(
        (f.x * xq.x - f.y * xq.y) * QS, (f.y * xq.x + f.x * xq.y) * QS);
    *(half2*)(g_k + out_off) = __floats2half2_rn(
        f.x * xk.x - f.y * xk.y, f.y * xk.x + f.x * xk.y);
    *(half2*)(g_v + out_off) = __floats2half2_rn(xv.x, xv.y);
}

// ---------------------------------------------------------------------------
// Flash attention. grid = (bh, q-tile [reversed]). 4 warps; warp w owns
// q rows [16w, 16w+16).
// ---------------------------------------------------------------------------
__global__ void __launch_bounds__(NTHREADS, 2)
attn_kernel(float* __restrict__ out) {
    __shared__ __align__(16) char smem[SMEM_BYTES];
    const uint32_t sb = smem_u32(smem);

    const int bh = blockIdx.x;
    const int qt = (int)(gridDim.y - 1) - (int)blockIdx.y;  // long rows first
    const int m0 = qt * BM;
    const int tid  = threadIdx.x;
    const int warp = tid >> 5;
    const int lane = tid & 31;
    const int g  = lane >> 2;
    const int t4 = lane & 3;

    const __half* Qg = g_q + (size_t)bh * S_ * D_;
    const __half* Kg = g_k + (size_t)bh * S_ * D_;
    const __half* Vg = g_v + (size_t)bh * S_ * D_;

    // ---- Stage Q tile (64 rows x 128) into smem (pitch 272B), rows 0..63
    //      live across OFF_K..OFF_V region (contiguous). ----
#pragma unroll
    for (int i = 0; i < 8; i++) {
        int idx = tid + i * 128;
        int r = idx >> 4, c = idx & 15;
        uint4 x = *(const uint4*)(Qg + (size_t)(m0 + r) * D_ + c * 8);
        *(uint4*)(smem + r * KPITCH_B + c * 16) = x;
    }
    __syncthreads();

    // ---- Q fragments: 8 ldmatrix.x4 per warp ----
    const uint32_t qaddr = sb + (warp * 16 + (lane & 15)) * KPITCH_B + (lane >> 4) * 16;
    uint32_t qa[8][4];
#pragma unroll
    for (int kf = 0; kf < 8; kf++) ldsm_x4(qa[kf], qaddr + kf * 32);

    // ---- per-thread ldmatrix base addresses ----
    const uint32_t kaddr = sb + OFF_K + ((lane >> 4) * 8 + (lane & 7)) * KPITCH_B
                         + ((lane >> 3) & 1) * 16;
    const uint32_t vaddr = sb + OFF_V + (((lane >> 3) & 1) * 8 + (lane & 7)) * KPITCH_B
                         + (lane >> 4) * 16;
    const uint32_t paddr = sb + OFF_P + (warp * 16 + (lane & 15)) * PPITCH_B
                         + (lane >> 4) * 16;

    float oacc[16][4];
#pragma unroll
    for (int i = 0; i < 16; i++) {
        oacc[i][0] = 0.f; oacc[i][1] = 0.f; oacc[i][2] = 0.f; oacc[i][3] = 0.f;
    }
    const int rl0 = warp * 16 + g;
    float mrow0 = -1e30f, mrow1 = -1e30f;
    float lrow0 = 0.f,    lrow1 = 0.f;

    const int ntiles = qt + 1;
    for (int t = 0; t < ntiles; t++) {
        const int n0 = t * BN;
        __syncthreads();   // previous tile fully consumed (and Q staging, t=0)

        // ---- Load K,V tiles: 64 rows x 128 halves each, coalesced 16B ----
#pragma unroll
        for (int i = 0; i < 8; i++) {
            int idx = tid + i * 128;
            int r = idx >> 4, c = idx & 15;
            uint4 xk = *(const uint4*)(Kg + (size_t)(n0 + r) * D_ + c * 8);
            *(uint4*)(smem + OFF_K + r * KPITCH_B + c * 16) = xk;
            uint4 xv = *(const uint4*)(Vg + (size_t)(n0 + r) * D_ + c * 8);
            *(uint4*)(smem + OFF_V + r * KPITCH_B + c * 16) = xv;
        }
        __syncthreads();

        // ---- S = Q K^T : 64 mma per warp, B via 32 ldmatrix.x4 ----
        float sacc[8][4];
#pragma unroll
        for (int i = 0; i < 8; i++) {
            sacc[i][0] = 0.f; sacc[i][1] = 0.f; sacc[i][2] = 0.f; sacc[i][3] = 0.f;
        }
#pragma unroll
        for (int np = 0; np < 4; np++) {
#pragma unroll
            for (int kf = 0; kf < 8; kf++) {
                uint32_t b[4];
                ldsm_x4(b, kaddr + np * (16 * KPITCH_B) + kf * 32);
                mma_f16(sacc[2 * np],     qa[kf], b[0], b[1]);
                mma_f16(sacc[2 * np + 1], qa[kf], b[2], b[3]);
            }
        }

        // ---- Causal mask (diagonal tile only) ----
        if (n0 == m0) {
#pragma unroll
            for (int nf = 0; nf < 8; nf++) {
                int c0 = nf * 8 + 2 * t4;
                if (c0     > rl0)     sacc[nf][0] = -1e30f;
                if (c0 + 1 > rl0)     sacc[nf][1] = -1e30f;
                if (c0     > rl0 + 8) sacc[nf][2] = -1e30f;
                if (c0 + 1 > rl0 + 8) sacc[nf][3] = -1e30f;
            }
        }

        // ---- Online softmax (scores already in log2 space) ----
        float tm0 = -1e30f, tm1 = -1e30f;
#pragma unroll
        for (int nf = 0; nf < 8; nf++) {
            tm0 = fmaxf(tm0, fmaxf(sacc[nf][0], sacc[nf][1]));
            tm1 = fmaxf(tm1, fmaxf(sacc[nf][2], sacc[nf][3]));
        }
        tm0 = fmaxf(tm0, __shfl_xor_sync(0xffffffffu, tm0, 1));
        tm0 = fmaxf(tm0, __shfl_xor_sync(0xffffffffu, tm0, 2));
        tm1 = fmaxf(tm1, __shfl_xor_sync(0xffffffffu, tm1, 1));
        tm1 = fmaxf(tm1, __shfl_xor_sync(0xffffffffu, tm1, 2));

        float mn0 = fmaxf(mrow0, tm0);
        float mn1 = fmaxf(mrow1, tm1);
        float alpha0 = fast_exp2(mrow0 - mn0);
        float alpha1 = fast_exp2(mrow1 - mn1);
        mrow0 = mn0; mrow1 = mn1;

        float rs0 = 0.f, rs1 = 0.f;
#pragma unroll
        for (int nf = 0; nf < 8; nf++) {
            sacc[nf][0] = fast_exp2(sacc[nf][0] - mn0);
            sacc[nf][1] = fast_exp2(sacc[nf][1] - mn0);
            sacc[nf][2] = fast_exp2(sacc[nf][2] - mn1);
            sacc[nf][3] = fast_exp2(sacc[nf][3] - mn1);
            rs0 += sacc[nf][0] + sacc[nf][1];
            rs1 += sacc[nf][2] + sacc[nf][3];
        }
        rs0 += __shfl_xor_sync(0xffffffffu, rs0, 1);
        rs0 += __shfl_xor_sync(0xffffffffu, rs0, 2);
        rs1 += __shfl_xor_sync(0xffffffffu, rs1, 1);
        rs1 += __shfl_xor_sync(0xffffffffu, rs1, 2);
        lrow0 = lrow0 * alpha0 + rs0;
        lrow1 = lrow1 * alpha1 + rs1;

#pragma unroll
        for (int nf = 0; nf < 16; nf++) {
            oacc[nf][0] *= alpha0; oacc[nf][1] *= alpha0;
            oacc[nf][2] *= alpha1; oacc[nf][3] *= alpha1;
        }

        // ---- P -> shared as fp16 (warp-private rows), conflict-free ----
#pragma unroll
        for (int nf = 0; nf < 8; nf++) {
            *(half2*)(smem + OFF_P + rl0 * PPITCH_B + (nf * 8 + 2 * t4) * 2) =
                __floats2half2_rn(sacc[nf][0], sacc[nf][1]);
            *(half2*)(smem + OFF_P + (rl0 + 8) * PPITCH_B + (nf * 8 + 2 * t4) * 2) =
                __floats2half2_rn(sacc[nf][2], sacc[nf][3]);
        }
        __syncwarp();

        // ---- O += P V : A via ldmatrix(P), B via ldmatrix.trans(V) ----
#pragma unroll
        for (int kf = 0; kf < 4; kf++) {
            uint32_t pa[4];
            ldsm_x4(pa, paddr + kf * 32);
#pragma unroll
            for (int np = 0; np < 8; np++) {
                uint32_t vb[4];
                ldsm_x4_t(vb, vaddr + kf * (16 * KPITCH_B) + np * 32);
                mma_f16(oacc[2 * np],     pa, vb[0], vb[1]);
                mma_f16(oacc[2 * np + 1], pa, vb[2], vb[3]);
            }
        }
    }

    // ---- Epilogue: normalize and store (B,H,S,D) ----
    float inv0 = 1.0f / lrow0;
    float inv1 = 1.0f / lrow1;
    float* o0 = out + ((size_t)bh * S_ + (m0 + rl0)) * D_;
    float* o1 = out + ((size_t)bh * S_ + (m0 + rl0 + 8)) * D_;
#pragma unroll
    for (int nf = 0; nf < 16; nf++) {
        int c = nf * 8 + 2 * t4;
        *(float2*)(o0 + c) = make_float2(oacc[nf][0] * inv0, oacc[nf][1] * inv0);
        *(float2*)(o1 + c) = make_float2(oacc[nf][2] * inv1, oacc[nf][3] * inv1);
    }
}

// ---------------------------------------------------------------------------
extern "C" void kernel_launch(void* const* d_in, const int* in_sizes, int n_in,
                              void* d_out, int out_size) {
    const float* q     = (const float*)d_in[0];
    const float* k     = (const float*)d_in[1];
    const float* v     = (const float*)d_in[2];
    const float* freqs = (const float*)d_in[3];
    float* out = (float*)d_out;
    (void)in_sizes; (void)n_in; (void)out_size;

    const int TOTAL_PAIRS = B_ * S_ * H_ * (D_ / 2);
    rope_prep_kernel<<<TOTAL_PAIRS / 256, 256>>>(q, k, v, freqs);

    dim3 grid(BH_, S_ / BM);
    attn_kernel<<<grid, NTHREADS>>>(out);
}

// round 6
// speedup vs baseline: 2.0515x; 1.1175x over previous
#include <cuda_runtime.h>
#include <cuda_fp16.h>
#include <cstdint>

// ---------------------------------------------------------------------------
// PatternCWanRoPE R6: fp16 warp-MMA flash attention (m16n8k16) + ldmatrix
//   + register P-pass (no P SMEM round-trip)
//   + cp.async double-buffered K/V pipeline (LDG latency hidden).
//   q,k,v : (B=2, S=2048, H=16, D=128) fp32   freqs : (1,S,1,D)
//   out   : (B,H,S,D) fp32
// ---------------------------------------------------------------------------

#define B_ 2
#define S_ 2048
#define H_ 16
#define D_ 128
#define BH_ 32

#define BM 64
#define BN 64
#define NTHREADS 128

#define KPITCH_B 272              // 136 halves/row (128 data + 8 pad); 17x16B
#define TILE_B   (64 * KPITCH_B)  // 17408 bytes per K or V tile
#define OFF_Q    0
#define OFF_B0   TILE_B           // buf0: K at +0, V at +TILE_B
#define OFF_B1   (OFF_B0 + 2 * TILE_B)
#define SMEM_BYTES (OFF_B1 + 2 * TILE_B)   // 87040

// fp16 scratch in (B,H,S,D): rope'd Q (pre-scaled by 1/sqrt(D)*log2e), K, V.
__device__ __half g_q[(size_t)BH_ * S_ * D_];
__device__ __half g_k[(size_t)BH_ * S_ * D_];
__device__ __half g_v[(size_t)BH_ * S_ * D_];

// ---------------------------------------------------------------------------
__device__ __forceinline__ uint32_t smem_u32(const void* p) {
    uint32_t a;
    asm("{ .reg .u64 t; cvta.to.shared.u64 t, %1; cvt.u32.u64 %0, t; }"
        : "=r"(a) : "l"(p));
    return a;
}
__device__ __forceinline__ float fast_exp2(float x) {
    float y; asm("ex2.approx.f32 %0, %1;" : "=f"(y) : "f"(x));
    return y;
}
__device__ __forceinline__ uint32_t h2pack(float a, float b) {
    __half2 h = __floats2half2_rn(a, b);
    return *reinterpret_cast<uint32_t*>(&h);
}
__device__ __forceinline__ void ldsm_x4(uint32_t r[4], uint32_t a) {
    asm volatile("ldmatrix.sync.aligned.m8n8.x4.shared.b16 {%0,%1,%2,%3}, [%4];"
                 : "=r"(r[0]), "=r"(r[1]), "=r"(r[2]), "=r"(r[3]) : "r"(a));
}
__device__ __forceinline__ void ldsm_x4_t(uint32_t r[4], uint32_t a) {
    asm volatile("ldmatrix.sync.aligned.m8n8.x4.trans.shared.b16 {%0,%1,%2,%3}, [%4];"
                 : "=r"(r[0]), "=r"(r[1]), "=r"(r[2]), "=r"(r[3]) : "r"(a));
}
__device__ __forceinline__ void mma_f16(float c[4], const uint32_t a[4],
                                        uint32_t b0, uint32_t b1) {
    asm volatile(
        "mma.sync.aligned.m16n8k16.row.col.f32.f16.f16.f32 "
        "{%0,%1,%2,%3}, {%4,%5,%6,%7}, {%8,%9}, {%0,%1,%2,%3};\n"
        : "+f"(c[0]), "+f"(c[1]), "+f"(c[2]), "+f"(c[3])
        : "r"(a[0]), "r"(a[1]), "r"(a[2]), "r"(a[3]), "r"(b0), "r"(b1));
}
#define CP_COMMIT() asm volatile("cp.async.commit_group;" ::: "memory")
#define CP_WAIT1()  asm volatile("cp.async.wait_group 1;" ::: "memory")
#define CP_WAIT0()  asm volatile("cp.async.wait_group 0;" ::: "memory")

// Prefetch one 64x128 fp16 K tile + V tile into SMEM buffer (one group).
__device__ __forceinline__ void cp_tile(const __half* __restrict__ Kg,
                                        const __half* __restrict__ Vg,
                                        uint32_t kbuf, uint32_t vbuf,
                                        int n0, int tid) {
#pragma unroll
    for (int i = 0; i < 8; i++) {
        int idx = tid + i * 128;
        int r = idx >> 4, c = idx & 15;
        uint32_t d = (uint32_t)(r * KPITCH_B + c * 16);
        asm volatile("cp.async.cg.shared.global [%0], [%1], 16;"
                     :: "r"(kbuf + d), "l"(Kg + (size_t)(n0 + r) * D_ + c * 8));
        asm volatile("cp.async.cg.shared.global [%0], [%1], 16;"
                     :: "r"(vbuf + d), "l"(Vg + (size_t)(n0 + r) * D_ + c * 8));
    }
    CP_COMMIT();
}

// ---------------------------------------------------------------------------
// Prologue: RoPE(q,k) + scale, fp16 convert, (B,S,H,D)->(B,H,S,D). V too.
// ---------------------------------------------------------------------------
__global__ void rope_prep_kernel(const float* __restrict__ q,
                                 const float* __restrict__ k,
                                 const float* __restrict__ v,
                                 const float* __restrict__ freqs) {
    int pid = blockIdx.x * blockDim.x + threadIdx.x;
    int dp = pid & 63;
    int h  = (pid >> 6) & (H_ - 1);
    int s  = (pid >> 10) & (S_ - 1);
    int b  = pid >> 21;

    size_t in_off  = ((((size_t)b * S_ + s) * H_ + h) * D_) + 2 * dp;
    size_t f_off   = (size_t)s * D_ + 2 * dp;
    size_t out_off = ((((size_t)b * H_ + h) * S_ + s) * D_) + 2 * dp;

    float2 f  = *(const float2*)(freqs + f_off);
    float2 xq = *(const float2*)(q + in_off);
    float2 xk = *(const float2*)(k + in_off);
    float2 xv = *(const float2*)(v + in_off);

    const float QS = 0.08838834764831845f * 1.4426950408889634f; // 1/sqrt(D)*log2e

    *(half2*)(g_q + out_off) = __floats2half2_rn(
        (f.x * xq.x - f.y * xq.y) * QS, (f.y * xq.x + f.x * xq.y) * QS);
    *(half2*)(g_k + out_off) = __floats2half2_rn(
        f.x * xk.x - f.y * xk.y, f.y * xk.x + f.x * xk.y);
    *(half2*)(g_v + out_off) = __floats2half2_rn(xv.x, xv.y);
}

// ---------------------------------------------------------------------------
// Flash attention. grid = (bh, q-tile [reversed]). 4 warps; warp w owns
// q rows [16w, 16w+16).
// ---------------------------------------------------------------------------
__global__ void __launch_bounds__(NTHREADS, 2)
attn_kernel(float* __restrict__ out) {
    extern __shared__ __align__(16) char smem[];
    const uint32_t sb = smem_u32(smem);

    const int bh = blockIdx.x;
    const int qt = (int)(gridDim.y - 1) - (int)blockIdx.y;  // long rows first
    const int m0 = qt * BM;
    const int tid  = threadIdx.x;
    const int warp = tid >> 5;
    const int lane = tid & 31;
    const int g  = lane >> 2;
    const int t4 = lane & 3;

    const __half* Qg = g_q + (size_t)bh * S_ * D_;
    const __half* Kg = g_k + (size_t)bh * S_ * D_;
    const __half* Vg = g_v + (size_t)bh * S_ * D_;

    // Kick off tile 0 prefetch immediately (overlaps Q staging below).
    cp_tile(Kg, Vg, sb + OFF_B0, sb + OFF_B0 + TILE_B, 0, tid);

    // ---- Stage Q tile (64 x 128) at OFF_Q, then load fragments ----
#pragma unroll
    for (int i = 0; i < 8; i++) {
        int idx = tid + i * 128;
        int r = idx >> 4, c = idx & 15;
        uint4 x = *(const uint4*)(Qg + (size_t)(m0 + r) * D_ + c * 8);
        *(uint4*)(smem + OFF_Q + r * KPITCH_B + c * 16) = x;
    }
    __syncthreads();

    const uint32_t qaddr = sb + OFF_Q + (warp * 16 + (lane & 15)) * KPITCH_B
                         + (lane >> 4) * 16;
    uint32_t qa[8][4];
#pragma unroll
    for (int kf = 0; kf < 8; kf++) ldsm_x4(qa[kf], qaddr + kf * 32);

    // per-thread ldmatrix lane offsets (within a K / V tile)
    const uint32_t koff = ((lane >> 4) * 8 + (lane & 7)) * KPITCH_B
                        + ((lane >> 3) & 1) * 16;
    const uint32_t voff = (((lane >> 3) & 1) * 8 + (lane & 7)) * KPITCH_B
                        + (lane >> 4) * 16;

    float oacc[16][4];
#pragma unroll
    for (int i = 0; i < 16; i++) {
        oacc[i][0] = 0.f; oacc[i][1] = 0.f; oacc[i][2] = 0.f; oacc[i][3] = 0.f;
    }
    const int rl0 = warp * 16 + g;
    float mrow0 = -1e30f, mrow1 = -1e30f;
    float lrow0 = 0.f,    lrow1 = 0.f;

    const int ntiles = qt + 1;
    for (int t = 0; t < ntiles; t++) {
        const uint32_t bufo = (t & 1) ? OFF_B1 : OFF_B0;

        // Prefetch next tile into the other buffer, then wait for current.
        if (t + 1 < ntiles) {
            const uint32_t nb = ((t + 1) & 1) ? OFF_B1 : OFF_B0;
            cp_tile(Kg, Vg, sb + nb, sb + nb + TILE_B, (t + 1) * BN, tid);
            CP_WAIT1();
        } else {
            CP_WAIT0();
        }
        __syncthreads();   // current buffer visible to all warps

        const uint32_t kbase = sb + bufo + koff;
        const uint32_t vbase = sb + bufo + TILE_B + voff;

        // ---- S = Q K^T : 64 mma per warp ----
        float sacc[8][4];
#pragma unroll
        for (int i = 0; i < 8; i++) {
            sacc[i][0] = 0.f; sacc[i][1] = 0.f; sacc[i][2] = 0.f; sacc[i][3] = 0.f;
        }
#pragma unroll
        for (int np = 0; np < 4; np++) {
#pragma unroll
            for (int kf = 0; kf < 8; kf++) {
                uint32_t b[4];
                ldsm_x4(b, kbase + np * (16 * KPITCH_B) + kf * 32);
                mma_f16(sacc[2 * np],     qa[kf], b[0], b[1]);
                mma_f16(sacc[2 * np + 1], qa[kf], b[2], b[3]);
            }
        }

        // ---- Causal mask (diagonal tile only) ----
        if (t == qt) {
#pragma unroll
            for (int nf = 0; nf < 8; nf++) {
                int c0 = nf * 8 + 2 * t4;
                if (c0     > rl0)     sacc[nf][0] = -1e30f;
                if (c0 + 1 > rl0)     sacc[nf][1] = -1e30f;
                if (c0     > rl0 + 8) sacc[nf][2] = -1e30f;
                if (c0 + 1 > rl0 + 8) sacc[nf][3] = -1e30f;
            }
        }

        // ---- Online softmax (scores already in log2 space) ----
        float tm0 = -1e30f, tm1 = -1e30f;
#pragma unroll
        for (int nf = 0; nf < 8; nf++) {
            tm0 = fmaxf(tm0, fmaxf(sacc[nf][0], sacc[nf][1]));
            tm1 = fmaxf(tm1, fmaxf(sacc[nf][2], sacc[nf][3]));
        }
        tm0 = fmaxf(tm0, __shfl_xor_sync(0xffffffffu, tm0, 1));
        tm0 = fmaxf(tm0, __shfl_xor_sync(0xffffffffu, tm0, 2));
        tm1 = fmaxf(tm1, __shfl_xor_sync(0xffffffffu, tm1, 1));
        tm1 = fmaxf(tm1, __shfl_xor_sync(0xffffffffu, tm1, 2));

        float mn0 = fmaxf(mrow0, tm0);
        float mn1 = fmaxf(mrow1, tm1);
        float alpha0 = fast_exp2(mrow0 - mn0);
        float alpha1 = fast_exp2(mrow1 - mn1);
        mrow0 = mn0; mrow1 = mn1;

        float rs0 = 0.f, rs1 = 0.f;
#pragma unroll
        for (int nf = 0; nf < 8; nf++) {
            sacc[nf][0] = fast_exp2(sacc[nf][0] - mn0);
            sacc[nf][1] = fast_exp2(sacc[nf][1] - mn0);
            sacc[nf][2] = fast_exp2(sacc[nf][2] - mn1);
            sacc[nf][3] = fast_exp2(sacc[nf][3] - mn1);
            rs0 += sacc[nf][0] + sacc[nf][1];
            rs1 += sacc[nf][2] + sacc[nf][3];
        }
        rs0 += __shfl_xor_sync(0xffffffffu, rs0, 1);
        rs0 += __shfl_xor_sync(0xffffffffu, rs0, 2);
        rs1 += __shfl_xor_sync(0xffffffffu, rs1, 1);
        rs1 += __shfl_xor_sync(0xffffffffu, rs1, 2);
        lrow0 = lrow0 * alpha0 + rs0;
        lrow1 = lrow1 * alpha1 + rs1;

#pragma unroll
        for (int nf = 0; nf < 16; nf++) {
            oacc[nf][0] *= alpha0; oacc[nf][1] *= alpha0;
            oacc[nf][2] *= alpha1; oacc[nf][3] *= alpha1;
        }

        // ---- O += P V : A fragments packed directly from sacc (no SMEM) ----
#pragma unroll
        for (int kf = 0; kf < 4; kf++) {
            uint32_t pa[4];
            pa[0] = h2pack(sacc[2 * kf][0],     sacc[2 * kf][1]);
            pa[1] = h2pack(sacc[2 * kf][2],     sacc[2 * kf][3]);
            pa[2] = h2pack(sacc[2 * kf + 1][0], sacc[2 * kf + 1][1]);
            pa[3] = h2pack(sacc[2 * kf + 1][2], sacc[2 * kf + 1][3]);
#pragma unroll
            for (int np = 0; np < 8; np++) {
                uint32_t vb[4];
                ldsm_x4_t(vb, vbase + kf * (16 * KPITCH_B) + np * 32);
                mma_f16(oacc[2 * np],     pa, vb[0], vb[1]);
                mma_f16(oacc[2 * np + 1], pa, vb[2], vb[3]);
            }
        }
        __syncthreads();   // all reads of this buffer done before its refill
    }

    // ---- Epilogue: normalize and store (B,H,S,D) ----
    float inv0 = 1.0f / lrow0;
    float inv1 = 1.0f / lrow1;
    float* o0 = out + ((size_t)bh * S_ + (m0 + rl0)) * D_;
    float* o1 = out + ((size_t)bh * S_ + (m0 + rl0 + 8)) * D_;
#pragma unroll
    for (int nf = 0; nf < 16; nf++) {
        int c = nf * 8 + 2 * t4;
        *(float2*)(o0 + c) = make_float2(oacc[nf][0] * inv0, oacc[nf][1] * inv0);
        *(float2*)(o1 + c) = make_float2(oacc[nf][2] * inv1, oacc[nf][3] * inv1);
    }
}

// ---------------------------------------------------------------------------
extern "C" void kernel_launch(void* const* d_in, const int* in_sizes, int n_in,
                              void* d_out, int out_size) {
    const float* q     = (const float*)d_in[0];
    const float* k     = (const float*)d_in[1];
    const float* v     = (const float*)d_in[2];
    const float* freqs = (const float*)d_in[3];
    float* out = (float*)d_out;
    (void)in_sizes; (void)n_in; (void)out_size;

    cudaFuncSetAttribute(attn_kernel,
                         cudaFuncAttributeMaxDynamicSharedMemorySize, SMEM_BYTES);

    const int TOTAL_PAIRS = B_ * S_ * H_ * (D_ / 2);
    rope_prep_kernel<<<TOTAL_PAIRS / 256, 256>>>(q, k, v, freqs);

    dim3 grid(BH_, S_ / BM);
    attn_kernel<<<grid, NTHREADS, SMEM_BYTES>>>(out);
}

// round 8
// speedup vs baseline: 2.0859x; 1.0168x over previous
#include <cuda_runtime.h>
#include <cuda_fp16.h>
#include <cstdint>

// ---------------------------------------------------------------------------
// PatternCWanRoPE R8: fp16 warp-MMA flash attention (m16n8k16) + ldmatrix
//   + register P-pass + cp.async double-buffered K/V pipeline
//   + ONLINE-max softmax (scores ~N(0,2.9) log2 -> max-free overflows fp16)
//     with alpha-skip rescale + deferred (epilogue) sum reduction
//   + vectorized RoPE prologue.
//   q,k,v : (B=2, S=2048, H=16, D=128) fp32   freqs : (1,S,1,D)
//   out   : (B,H,S,D) fp32
// ---------------------------------------------------------------------------

#define B_ 2
#define S_ 2048
#define H_ 16
#define D_ 128
#define BH_ 32

#define BM 64
#define BN 64
#define NTHREADS 128

#define KPITCH_B 272              // 136 halves/row (128 data + 8 pad); 17x16B
#define TILE_B   (64 * KPITCH_B)  // 17408 bytes per K or V tile
#define OFF_Q    0
#define OFF_B0   TILE_B           // buf0: K at +0, V at +TILE_B
#define OFF_B1   (OFF_B0 + 2 * TILE_B)
#define SMEM_BYTES (OFF_B1 + 2 * TILE_B)   // 87040

// fp16 scratch in (B,H,S,D): rope'd Q (pre-scaled by 1/sqrt(D)*log2e), K, V.
__device__ __half g_q[(size_t)BH_ * S_ * D_];
__device__ __half g_k[(size_t)BH_ * S_ * D_];
__device__ __half g_v[(size_t)BH_ * S_ * D_];

// ---------------------------------------------------------------------------
__device__ __forceinline__ uint32_t smem_u32(const void* p) {
    uint32_t a;
    asm("{ .reg .u64 t; cvta.to.shared.u64 t, %1; cvt.u32.u64 %0, t; }"
        : "=r"(a) : "l"(p));
    return a;
}
__device__ __forceinline__ float fast_exp2(float x) {
    float y; asm("ex2.approx.f32 %0, %1;" : "=f"(y) : "f"(x));
    return y;
}
__device__ __forceinline__ uint32_t h2pack(float a, float b) {
    __half2 h = __floats2half2_rn(a, b);
    return *reinterpret_cast<uint32_t*>(&h);
}
__device__ __forceinline__ void ldsm_x4(uint32_t r[4], uint32_t a) {
    asm volatile("ldmatrix.sync.aligned.m8n8.x4.shared.b16 {%0,%1,%2,%3}, [%4];"
                 : "=r"(r[0]), "=r"(r[1]), "=r"(r[2]), "=r"(r[3]) : "r"(a));
}
__device__ __forceinline__ void ldsm_x4_t(uint32_t r[4], uint32_t a) {
    asm volatile("ldmatrix.sync.aligned.m8n8.x4.trans.shared.b16 {%0,%1,%2,%3}, [%4];"
                 : "=r"(r[0]), "=r"(r[1]), "=r"(r[2]), "=r"(r[3]) : "r"(a));
}
__device__ __forceinline__ void mma_f16(float c[4], const uint32_t a[4],
                                        uint32_t b0, uint32_t b1) {
    asm volatile(
        "mma.sync.aligned.m16n8k16.row.col.f32.f16.f16.f32 "
        "{%0,%1,%2,%3}, {%4,%5,%6,%7}, {%8,%9}, {%0,%1,%2,%3};\n"
        : "+f"(c[0]), "+f"(c[1]), "+f"(c[2]), "+f"(c[3])
        : "r"(a[0]), "r"(a[1]), "r"(a[2]), "r"(a[3]), "r"(b0), "r"(b1));
}
#define CP_COMMIT() asm volatile("cp.async.commit_group;" ::: "memory")
#define CP_WAIT1()  asm volatile("cp.async.wait_group 1;" ::: "memory")
#define CP_WAIT0()  asm volatile("cp.async.wait_group 0;" ::: "memory")

// Prefetch one 64x128 fp16 K tile + V tile into SMEM buffer (one group).
__device__ __forceinline__ void cp_tile(const __half* __restrict__ Kg,
                                        const __half* __restrict__ Vg,
                                        uint32_t kbuf, uint32_t vbuf,
                                        int n0, int tid) {
#pragma unroll
    for (int i = 0; i < 8; i++) {
        int idx = tid + i * 128;
        int r = idx >> 4, c = idx & 15;
        uint32_t d = (uint32_t)(r * KPITCH_B + c * 16);
        asm volatile("cp.async.cg.shared.global [%0], [%1], 16;"
                     :: "r"(kbuf + d), "l"(Kg + (size_t)(n0 + r) * D_ + c * 8));
        asm volatile("cp.async.cg.shared.global [%0], [%1], 16;"
                     :: "r"(vbuf + d), "l"(Vg + (size_t)(n0 + r) * D_ + c * 8));
    }
    CP_COMMIT();
}

// ---------------------------------------------------------------------------
// Prologue: RoPE(q,k) + scale, fp16 convert, (B,S,H,D)->(B,H,S,D). V too.
// 8 halves (4 interleaved pairs) per thread; fully vectorized.
// ---------------------------------------------------------------------------
__global__ void rope_prep_kernel(const float* __restrict__ q,
                                 const float* __restrict__ k,
                                 const float* __restrict__ v,
                                 const float* __restrict__ freqs) {
    int pid = blockIdx.x * blockDim.x + threadIdx.x;
    int d8 = pid & 15;               // 16 groups of 8 elements
    int h  = (pid >> 4) & (H_ - 1);
    int s  = (pid >> 8) & (S_ - 1);
    int b  = pid >> 19;

    size_t in_off  = ((((size_t)b * S_ + s) * H_ + h) * D_) + 8 * d8;
    size_t f_off   = (size_t)s * D_ + 8 * d8;
    size_t out_off = ((((size_t)b * H_ + h) * S_ + s) * D_) + 8 * d8;

    const float QS = 0.08838834764831845f * 1.4426950408889634f; // 1/sqrt(D)*log2e

    float4 f0 = *(const float4*)(freqs + f_off);
    float4 f1 = *(const float4*)(freqs + f_off + 4);
    float4 q0 = *(const float4*)(q + in_off);
    float4 q1 = *(const float4*)(q + in_off + 4);
    float4 k0 = *(const float4*)(k + in_off);
    float4 k1 = *(const float4*)(k + in_off + 4);
    float4 v0 = *(const float4*)(v + in_off);
    float4 v1 = *(const float4*)(v + in_off + 4);

    uint4 oq, ok, ov;
    oq.x = h2pack((f0.x * q0.x - f0.y * q0.y) * QS, (f0.y * q0.x + f0.x * q0.y) * QS);
    oq.y = h2pack((f0.z * q0.z - f0.w * q0.w) * QS, (f0.w * q0.z + f0.z * q0.w) * QS);
    oq.z = h2pack((f1.x * q1.x - f1.y * q1.y) * QS, (f1.y * q1.x + f1.x * q1.y) * QS);
    oq.w = h2pack((f1.z * q1.z - f1.w * q1.w) * QS, (f1.w * q1.z + f1.z * q1.w) * QS);
    ok.x = h2pack(f0.x * k0.x - f0.y * k0.y, f0.y * k0.x + f0.x * k0.y);
    ok.y = h2pack(f0.z * k0.z - f0.w * k0.w, f0.w * k0.z + f0.z * k0.w);
    ok.z = h2pack(f1.x * k1.x - f1.y * k1.y, f1.y * k1.x + f1.x * k1.y);
    ok.w = h2pack(f1.z * k1.z - f1.w * k1.w, f1.w * k1.z + f1.z * k1.w);
    ov.x = h2pack(v0.x, v0.y);
    ov.y = h2pack(v0.z, v0.w);
    ov.z = h2pack(v1.x, v1.y);
    ov.w = h2pack(v1.z, v1.w);

    *(uint4*)(g_q + out_off) = oq;
    *(uint4*)(g_k + out_off) = ok;
    *(uint4*)(g_v + out_off) = ov;
}

// ---------------------------------------------------------------------------
// Flash attention. grid = (bh, q-tile [reversed]). 4 warps; warp w owns
// q rows [16w, 16w+16).
// ---------------------------------------------------------------------------
__global__ void __launch_bounds__(NTHREADS, 2)
attn_kernel(float* __restrict__ out) {
    extern __shared__ __align__(16) char smem[];
    const uint32_t sb = smem_u32(smem);

    const int bh = blockIdx.x;
    const int qt = (int)(gridDim.y - 1) - (int)blockIdx.y;  // long rows first
    const int m0 = qt * BM;
    const int tid  = threadIdx.x;
    const int warp = tid >> 5;
    const int lane = tid & 31;
    const int g  = lane >> 2;
    const int t4 = lane & 3;

    const __half* Qg = g_q + (size_t)bh * S_ * D_;
    const __half* Kg = g_k + (size_t)bh * S_ * D_;
    const __half* Vg = g_v + (size_t)bh * S_ * D_;

    // Kick off tile 0 prefetch immediately (overlaps Q staging below).
    cp_tile(Kg, Vg, sb + OFF_B0, sb + OFF_B0 + TILE_B, 0, tid);

    // ---- Stage Q tile (64 x 128) at OFF_Q, then load fragments ----
#pragma unroll
    for (int i = 0; i < 8; i++) {
        int idx = tid + i * 128;
        int r = idx >> 4, c = idx & 15;
        uint4 x = *(const uint4*)(Qg + (size_t)(m0 + r) * D_ + c * 8);
        *(uint4*)(smem + OFF_Q + r * KPITCH_B + c * 16) = x;
    }
    __syncthreads();

    const uint32_t qaddr = sb + OFF_Q + (warp * 16 + (lane & 15)) * KPITCH_B
                         + (lane >> 4) * 16;
    uint32_t qa[8][4];
#pragma unroll
    for (int kf = 0; kf < 8; kf++) ldsm_x4(qa[kf], qaddr + kf * 32);

    // per-thread ldmatrix lane offsets (within a K / V tile)
    const uint32_t koff = ((lane >> 4) * 8 + (lane & 7)) * KPITCH_B
                        + ((lane >> 3) & 1) * 16;
    const uint32_t voff = (((lane >> 3) & 1) * 8 + (lane & 7)) * KPITCH_B
                        + (lane >> 4) * 16;

    float oacc[16][4];
#pragma unroll
    for (int i = 0; i < 16; i++) {
        oacc[i][0] = 0.f; oacc[i][1] = 0.f; oacc[i][2] = 0.f; oacc[i][3] = 0.f;
    }
    const int rl0 = warp * 16 + g;
    float mrow0 = -1e30f, mrow1 = -1e30f;   // running row max (log2 space)
    float lrow0 = 0.f,    lrow1 = 0.f;      // per-thread partial row sums

    const int ntiles = qt + 1;
    for (int t = 0; t < ntiles; t++) {
        const uint32_t bufo = (t & 1) ? OFF_B1 : OFF_B0;

        // Prefetch next tile into the other buffer, then wait for current.
        if (t + 1 < ntiles) {
            const uint32_t nb = ((t + 1) & 1) ? OFF_B1 : OFF_B0;
            cp_tile(Kg, Vg, sb + nb, sb + nb + TILE_B, (t + 1) * BN, tid);
            CP_WAIT1();
        } else {
            CP_WAIT0();
        }
        __syncthreads();   // current buffer visible to all warps

        const uint32_t kbase = sb + bufo + koff;
        const uint32_t vbase = sb + bufo + TILE_B + voff;

        // ---- S = Q K^T : 64 mma per warp ----
        float sacc[8][4];
#pragma unroll
        for (int i = 0; i < 8; i++) {
            sacc[i][0] = 0.f; sacc[i][1] = 0.f; sacc[i][2] = 0.f; sacc[i][3] = 0.f;
        }
#pragma unroll
        for (int np = 0; np < 4; np++) {
#pragma unroll
            for (int kf = 0; kf < 8; kf++) {
                uint32_t b[4];
                ldsm_x4(b, kbase + np * (16 * KPITCH_B) + kf * 32);
                mma_f16(sacc[2 * np],     qa[kf], b[0], b[1]);
                mma_f16(sacc[2 * np + 1], qa[kf], b[2], b[3]);
            }
        }

        // ---- Causal mask (diagonal tile only) ----
        if (t == qt) {
#pragma unroll
            for (int nf = 0; nf < 8; nf++) {
                int c0 = nf * 8 + 2 * t4;
                if (c0     > rl0)     sacc[nf][0] = -1e30f;
                if (c0 + 1 > rl0)     sacc[nf][1] = -1e30f;
                if (c0     > rl0 + 8) sacc[nf][2] = -1e30f;
                if (c0 + 1 > rl0 + 8) sacc[nf][3] = -1e30f;
            }
        }

        // ---- Online softmax: row max via quad shuffle ----
        float tm0 = -1e30f, tm1 = -1e30f;
#pragma unroll
        for (int nf = 0; nf < 8; nf++) {
            tm0 = fmaxf(tm0, fmaxf(sacc[nf][0], sacc[nf][1]));
            tm1 = fmaxf(tm1, fmaxf(sacc[nf][2], sacc[nf][3]));
        }
        tm0 = fmaxf(tm0, __shfl_xor_sync(0xffffffffu, tm0, 1));
        tm0 = fmaxf(tm0, __shfl_xor_sync(0xffffffffu, tm0, 2));
        tm1 = fmaxf(tm1, __shfl_xor_sync(0xffffffffu, tm1, 1));
        tm1 = fmaxf(tm1, __shfl_xor_sync(0xffffffffu, tm1, 2));

        // Alpha-skip: rescale O / lrow only when the running max increases.
        // (Skipped path is bit-identical: alpha would be exactly 1.0.)
        if (tm0 > mrow0 || tm1 > mrow1) {
            float mn0 = fmaxf(mrow0, tm0);
            float mn1 = fmaxf(mrow1, tm1);
            float alpha0 = fast_exp2(mrow0 - mn0);
            float alpha1 = fast_exp2(mrow1 - mn1);
            mrow0 = mn0; mrow1 = mn1;
            lrow0 *= alpha0; lrow1 *= alpha1;
#pragma unroll
            for (int nf = 0; nf < 16; nf++) {
                oacc[nf][0] *= alpha0; oacc[nf][1] *= alpha0;
                oacc[nf][2] *= alpha1; oacc[nf][3] *= alpha1;
            }
        }

        // ---- P = exp2(S - m); per-thread partial sums (reduced at end) ----
        float a0 = 0.f, b0s = 0.f, a1 = 0.f, b1s = 0.f;
#pragma unroll
        for (int nf = 0; nf < 8; nf++) {
            sacc[nf][0] = fast_exp2(sacc[nf][0] - mrow0);
            sacc[nf][1] = fast_exp2(sacc[nf][1] - mrow0);
            sacc[nf][2] = fast_exp2(sacc[nf][2] - mrow1);
            sacc[nf][3] = fast_exp2(sacc[nf][3] - mrow1);
            a0  += sacc[nf][0]; b0s += sacc[nf][1];
            a1  += sacc[nf][2]; b1s += sacc[nf][3];
        }
        lrow0 += a0 + b0s;
        lrow1 += a1 + b1s;

        // ---- O += P V : A fragments packed directly from sacc (no SMEM) ----
#pragma unroll
        for (int kf = 0; kf < 4; kf++) {
            uint32_t pa[4];
            pa[0] = h2pack(sacc[2 * kf][0],     sacc[2 * kf][1]);
            pa[1] = h2pack(sacc[2 * kf][2],     sacc[2 * kf][3]);
            pa[2] = h2pack(sacc[2 * kf + 1][0], sacc[2 * kf + 1][1]);
            pa[3] = h2pack(sacc[2 * kf + 1][2], sacc[2 * kf + 1][3]);
#pragma unroll
            for (int np = 0; np < 8; np++) {
                uint32_t vb[4];
                ldsm_x4_t(vb, vbase + kf * (16 * KPITCH_B) + np * 32);
                mma_f16(oacc[2 * np],     pa, vb[0], vb[1]);
                mma_f16(oacc[2 * np + 1], pa, vb[2], vb[3]);
            }
        }
        __syncthreads();   // all reads of this buffer done before its refill
    }

    // ---- Epilogue: quad-reduce row sums once, normalize, store ----
    lrow0 += __shfl_xor_sync(0xffffffffu, lrow0, 1);
    lrow0 += __shfl_xor_sync(0xffffffffu, lrow0, 2);
    lrow1 += __shfl_xor_sync(0xffffffffu, lrow1, 1);
    lrow1 += __shfl_xor_sync(0xffffffffu, lrow1, 2);
    float inv0 = 1.0f / lrow0;
    float inv1 = 1.0f / lrow1;
    float* o0 = out + ((size_t)bh * S_ + (m0 + rl0)) * D_;
    float* o1 = out + ((size_t)bh * S_ + (m0 + rl0 + 8)) * D_;
#pragma unroll
    for (int nf = 0; nf < 16; nf++) {
        int c = nf * 8 + 2 * t4;
        *(float2*)(o0 + c) = make_float2(oacc[nf][0] * inv0, oacc[nf][1] * inv0);
        *(float2*)(o1 + c) = make_float2(oacc[nf][2] * inv1, oacc[nf][3] * inv1);
    }
}

// ---------------------------------------------------------------------------
extern "C" void kernel_launch(void* const* d_in, const int* in_sizes, int n_in,
                              void* d_out, int out_size) {
    const float* q     = (const float*)d_in[0];
    const float* k     = (const float*)d_in[1];
    const float* v     = (const float*)d_in[2];
    const float* freqs = (const float*)d_in[3];
    float* out = (float*)d_out;
    (void)in_sizes; (void)n_in; (void)out_size;

    cudaFuncSetAttribute(attn_kernel,
                         cudaFuncAttributeMaxDynamicSharedMemorySize, SMEM_BYTES);

    const int TOTAL8 = B_ * S_ * H_ * (D_ / 8);   // 1,048,576 threads
    rope_prep_kernel<<<TOTAL8 / 256, 256>>>(q, k, v, freqs);

    dim3 grid(BH_, S_ / BM);
    attn_kernel<<<grid, NTHREADS, SMEM_BYTES>>>(out);
}

// round 9
// speedup vs baseline: 2.1104x; 1.0118x over previous
#include <cuda_runtime.h>
#include <cuda_fp16.h>
#include <cstdint>

// ---------------------------------------------------------------------------
// PatternCWanRoPE R9: fp16 warp-MMA flash attention (m16n8k16) + ldmatrix
//   + register P-pass + cp.async double-buffered K/V pipeline
//   + SINGLE barrier per tile (wait_group0 -> sync -> cp-issue), giving each
//     warp a full-tile drift window so PV/QK tensor work overlaps other
//     warps' softmax phases.
//   q,k,v : (B=2, S=2048, H=16, D=128) fp32   freqs : (1,S,1,D)
//   out   : (B,H,S,D) fp32
// ---------------------------------------------------------------------------

#define B_ 2
#define S_ 2048
#define H_ 16
#define D_ 128
#define BH_ 32

#define BM 64
#define BN 64
#define NTHREADS 128

#define KPITCH_B 272              // 136 halves/row (128 data + 8 pad); 17x16B
#define TILE_B   (64 * KPITCH_B)  // 17408 bytes per K or V tile
#define OFF_Q    0
#define OFF_B0   TILE_B           // buf0: K at +0, V at +TILE_B
#define OFF_B1   (OFF_B0 + 2 * TILE_B)
#define SMEM_BYTES (OFF_B1 + 2 * TILE_B)   // 87040

// fp16 scratch in (B,H,S,D): rope'd Q (pre-scaled by 1/sqrt(D)*log2e), K, V.
__device__ __half g_q[(size_t)BH_ * S_ * D_];
__device__ __half g_k[(size_t)BH_ * S_ * D_];
__device__ __half g_v[(size_t)BH_ * S_ * D_];

// ---------------------------------------------------------------------------
__device__ __forceinline__ uint32_t smem_u32(const void* p) {
    uint32_t a;
    asm("{ .reg .u64 t; cvta.to.shared.u64 t, %1; cvt.u32.u64 %0, t; }"
        : "=r"(a) : "l"(p));
    return a;
}
__device__ __forceinline__ float fast_exp2(float x) {
    float y; asm("ex2.approx.f32 %0, %1;" : "=f"(y) : "f"(x));
    return y;
}
__device__ __forceinline__ uint32_t h2pack(float a, float b) {
    __half2 h = __floats2half2_rn(a, b);
    return *reinterpret_cast<uint32_t*>(&h);
}
__device__ __forceinline__ void ldsm_x4(uint32_t r[4], uint32_t a) {
    asm volatile("ldmatrix.sync.aligned.m8n8.x4.shared.b16 {%0,%1,%2,%3}, [%4];"
                 : "=r"(r[0]), "=r"(r[1]), "=r"(r[2]), "=r"(r[3]) : "r"(a));
}
__device__ __forceinline__ void ldsm_x4_t(uint32_t r[4], uint32_t a) {
    asm volatile("ldmatrix.sync.aligned.m8n8.x4.trans.shared.b16 {%0,%1,%2,%3}, [%4];"
                 : "=r"(r[0]), "=r"(r[1]), "=r"(r[2]), "=r"(r[3]) : "r"(a));
}
__device__ __forceinline__ void mma_f16(float c[4], const uint32_t a[4],
                                        uint32_t b0, uint32_t b1) {
    asm volatile(
        "mma.sync.aligned.m16n8k16.row.col.f32.f16.f16.f32 "
        "{%0,%1,%2,%3}, {%4,%5,%6,%7}, {%8,%9}, {%0,%1,%2,%3};\n"
        : "+f"(c[0]), "+f"(c[1]), "+f"(c[2]), "+f"(c[3])
        : "r"(a[0]), "r"(a[1]), "r"(a[2]), "r"(a[3]), "r"(b0), "r"(b1));
}
#define CP_COMMIT() asm volatile("cp.async.commit_group;" ::: "memory")
#define CP_WAIT0()  asm volatile("cp.async.wait_group 0;" ::: "memory")

// Prefetch one 64x128 fp16 K tile + V tile into SMEM buffer (one group).
__device__ __forceinline__ void cp_tile(const __half* __restrict__ Kg,
                                        const __half* __restrict__ Vg,
                                        uint32_t kbuf, uint32_t vbuf,
                                        int n0, int tid) {
#pragma unroll
    for (int i = 0; i < 8; i++) {
        int idx = tid + i * 128;
        int r = idx >> 4, c = idx & 15;
        uint32_t d = (uint32_t)(r * KPITCH_B + c * 16);
        asm volatile("cp.async.cg.shared.global [%0], [%1], 16;"
                     :: "r"(kbuf + d), "l"(Kg + (size_t)(n0 + r) * D_ + c * 8));
        asm volatile("cp.async.cg.shared.global [%0], [%1], 16;"
                     :: "r"(vbuf + d), "l"(Vg + (size_t)(n0 + r) * D_ + c * 8));
    }
    CP_COMMIT();
}

// ---------------------------------------------------------------------------
// Prologue: RoPE(q,k) + scale, fp16 convert, (B,S,H,D)->(B,H,S,D). V too.
// 8 halves (4 interleaved pairs) per thread; fully vectorized.
// ---------------------------------------------------------------------------
__global__ void rope_prep_kernel(const float* __restrict__ q,
                                 const float* __restrict__ k,
                                 const float* __restrict__ v,
                                 const float* __restrict__ freqs) {
    int pid = blockIdx.x * blockDim.x + threadIdx.x;
    int d8 = pid & 15;               // 16 groups of 8 elements
    int h  = (pid >> 4) & (H_ - 1);
    int s  = (pid >> 8) & (S_ - 1);
    int b  = pid >> 19;

    size_t in_off  = ((((size_t)b * S_ + s) * H_ + h) * D_) + 8 * d8;
    size_t f_off   = (size_t)s * D_ + 8 * d8;
    size_t out_off = ((((size_t)b * H_ + h) * S_ + s) * D_) + 8 * d8;

    const float QS = 0.08838834764831845f * 1.4426950408889634f; // 1/sqrt(D)*log2e

    float4 f0 = *(const float4*)(freqs + f_off);
    float4 f1 = *(const float4*)(freqs + f_off + 4);
    float4 q0 = *(const float4*)(q + in_off);
    float4 q1 = *(const float4*)(q + in_off + 4);
    float4 k0 = *(const float4*)(k + in_off);
    float4 k1 = *(const float4*)(k + in_off + 4);
    float4 v0 = *(const float4*)(v + in_off);
    float4 v1 = *(const float4*)(v + in_off + 4);

    uint4 oq, ok, ov;
    oq.x = h2pack((f0.x * q0.x - f0.y * q0.y) * QS, (f0.y * q0.x + f0.x * q0.y) * QS);
    oq.y = h2pack((f0.z * q0.z - f0.w * q0.w) * QS, (f0.w * q0.z + f0.z * q0.w) * QS);
    oq.z = h2pack((f1.x * q1.x - f1.y * q1.y) * QS, (f1.y * q1.x + f1.x * q1.y) * QS);
    oq.w = h2pack((f1.z * q1.z - f1.w * q1.w) * QS, (f1.w * q1.z + f1.z * q1.w) * QS);
    ok.x = h2pack(f0.x * k0.x - f0.y * k0.y, f0.y * k0.x + f0.x * k0.y);
    ok.y = h2pack(f0.z * k0.z - f0.w * k0.w, f0.w * k0.z + f0.z * k0.w);
    ok.z = h2pack(f1.x * k1.x - f1.y * k1.y, f1.y * k1.x + f1.x * k1.y);
    ok.w = h2pack(f1.z * k1.z - f1.w * k1.w, f1.w * k1.z + f1.z * k1.w);
    ov.x = h2pack(v0.x, v0.y);
    ov.y = h2pack(v0.z, v0.w);
    ov.z = h2pack(v1.x, v1.y);
    ov.w = h2pack(v1.z, v1.w);

    *(uint4*)(g_q + out_off) = oq;
    *(uint4*)(g_k + out_off) = ok;
    *(uint4*)(g_v + out_off) = ov;
}

// ---------------------------------------------------------------------------
// Flash attention. grid = (bh, q-tile [reversed]). 4 warps; warp w owns
// q rows [16w, 16w+16). ONE __syncthreads per tile.
// ---------------------------------------------------------------------------
__global__ void __launch_bounds__(NTHREADS, 2)
attn_kernel(float* __restrict__ out) {
    extern __shared__ __align__(16) char smem[];
    const uint32_t sb = smem_u32(smem);

    const int bh = blockIdx.x;
    const int qt = (int)(gridDim.y - 1) - (int)blockIdx.y;  // long rows first
    const int m0 = qt * BM;
    const int tid  = threadIdx.x;
    const int warp = tid >> 5;
    const int lane = tid & 31;
    const int g  = lane >> 2;
    const int t4 = lane & 3;

    const __half* Qg = g_q + (size_t)bh * S_ * D_;
    const __half* Kg = g_k + (size_t)bh * S_ * D_;
    const __half* Vg = g_v + (size_t)bh * S_ * D_;

    // Kick off tile 0 prefetch immediately (overlaps Q staging below).
    cp_tile(Kg, Vg, sb + OFF_B0, sb + OFF_B0 + TILE_B, 0, tid);

    // ---- Stage Q tile (64 x 128) at OFF_Q, then load fragments ----
#pragma unroll
    for (int i = 0; i < 8; i++) {
        int idx = tid + i * 128;
        int r = idx >> 4, c = idx & 15;
        uint4 x = *(const uint4*)(Qg + (size_t)(m0 + r) * D_ + c * 8);
        *(uint4*)(smem + OFF_Q + r * KPITCH_B + c * 16) = x;
    }
    __syncthreads();   // Q visible to all warps

    const uint32_t qaddr = sb + OFF_Q + (warp * 16 + (lane & 15)) * KPITCH_B
                         + (lane >> 4) * 16;
    uint32_t qa[8][4];
#pragma unroll
    for (int kf = 0; kf < 8; kf++) ldsm_x4(qa[kf], qaddr + kf * 32);

    // per-thread ldmatrix lane offsets (within a K / V tile)
    const uint32_t koff = ((lane >> 4) * 8 + (lane & 7)) * KPITCH_B
                        + ((lane >> 3) & 1) * 16;
    const uint32_t voff = (((lane >> 3) & 1) * 8 + (lane & 7)) * KPITCH_B
                        + (lane >> 4) * 16;

    float oacc[16][4];
#pragma unroll
    for (int i = 0; i < 16; i++) {
        oacc[i][0] = 0.f; oacc[i][1] = 0.f; oacc[i][2] = 0.f; oacc[i][3] = 0.f;
    }
    const int rl0 = warp * 16 + g;
    float mrow0 = -1e30f, mrow1 = -1e30f;   // running row max (log2 space)
    float lrow0 = 0.f,    lrow1 = 0.f;      // per-thread partial row sums

    const int ntiles = qt + 1;
    for (int t = 0; t < ntiles; t++) {
        const uint32_t bufo = (t & 1) ? OFF_B1 : OFF_B0;

        // ---- Single barrier point per tile ----
        // 1) my tile-t cp groups have landed; 2) barrier publishes everyone's
        // tile-t data AND guarantees all warps finished reading the buffer we
        // are about to refill (last read in iter t-1).
        CP_WAIT0();
        __syncthreads();
        if (t + 1 < ntiles) {
            const uint32_t nb = ((t + 1) & 1) ? OFF_B1 : OFF_B0;
            cp_tile(Kg, Vg, sb + nb, sb + nb + TILE_B, (t + 1) * BN, tid);
        }

        const uint32_t kbase = sb + bufo + koff;
        const uint32_t vbase = sb + bufo + TILE_B + voff;

        // ---- S = Q K^T : 64 mma per warp ----
        float sacc[8][4];
#pragma unroll
        for (int i = 0; i < 8; i++) {
            sacc[i][0] = 0.f; sacc[i][1] = 0.f; sacc[i][2] = 0.f; sacc[i][3] = 0.f;
        }
#pragma unroll
        for (int np = 0; np < 4; np++) {
#pragma unroll
            for (int kf = 0; kf < 8; kf++) {
                uint32_t b[4];
                ldsm_x4(b, kbase + np * (16 * KPITCH_B) + kf * 32);
                mma_f16(sacc[2 * np],     qa[kf], b[0], b[1]);
                mma_f16(sacc[2 * np + 1], qa[kf], b[2], b[3]);
            }
        }

        // ---- Causal mask (diagonal tile only) ----
        if (t == qt) {
#pragma unroll
            for (int nf = 0; nf < 8; nf++) {
                int c0 = nf * 8 + 2 * t4;
                if (c0     > rl0)     sacc[nf][0] = -1e30f;
                if (c0 + 1 > rl0)     sacc[nf][1] = -1e30f;
                if (c0     > rl0 + 8) sacc[nf][2] = -1e30f;
                if (c0 + 1 > rl0 + 8) sacc[nf][3] = -1e30f;
            }
        }

        // ---- Online softmax: row max via quad shuffle ----
        float tm0 = -1e30f, tm1 = -1e30f;
#pragma unroll
        for (int nf = 0; nf < 8; nf++) {
            tm0 = fmaxf(tm0, fmaxf(sacc[nf][0], sacc[nf][1]));
            tm1 = fmaxf(tm1, fmaxf(sacc[nf][2], sacc[nf][3]));
        }
        tm0 = fmaxf(tm0, __shfl_xor_sync(0xffffffffu, tm0, 1));
        tm0 = fmaxf(tm0, __shfl_xor_sync(0xffffffffu, tm0, 2));
        tm1 = fmaxf(tm1, __shfl_xor_sync(0xffffffffu, tm1, 1));
        tm1 = fmaxf(tm1, __shfl_xor_sync(0xffffffffu, tm1, 2));

        // Alpha-skip: rescale O / lrow only when the running max increases.
        // (Skipped path is bit-identical: alpha would be exactly 1.0.)
        if (tm0 > mrow0 || tm1 > mrow1) {
            float mn0 = fmaxf(mrow0, tm0);
            float mn1 = fmaxf(mrow1, tm1);
            float alpha0 = fast_exp2(mrow0 - mn0);
            float alpha1 = fast_exp2(mrow1 - mn1);
            mrow0 = mn0; mrow1 = mn1;
            lrow0 *= alpha0; lrow1 *= alpha1;
#pragma unroll
            for (int nf = 0; nf < 16; nf++) {
                oacc[nf][0] *= alpha0; oacc[nf][1] *= alpha0;
                oacc[nf][2] *= alpha1; oacc[nf][3] *= alpha1;
            }
        }

        // ---- P = exp2(S - m); per-thread partial sums (reduced at end) ----
        float a0 = 0.f, b0s = 0.f, a1 = 0.f, b1s = 0.f;
#pragma unroll
        for (int nf = 0; nf < 8; nf++) {
            sacc[nf][0] = fast_exp2(sacc[nf][0] - mrow0);
            sacc[nf][1] = fast_exp2(sacc[nf][1] - mrow0);
            sacc[nf][2] = fast_exp2(sacc[nf][2] - mrow1);
            sacc[nf][3] = fast_exp2(sacc[nf][3] - mrow1);
            a0  += sacc[nf][0]; b0s += sacc[nf][1];
            a1  += sacc[nf][2]; b1s += sacc[nf][3];
        }
        lrow0 += a0 + b0s;
        lrow1 += a1 + b1s;

        // ---- O += P V : A fragments packed directly from sacc (no SMEM) ----
#pragma unroll
        for (int kf = 0; kf < 4; kf++) {
            uint32_t pa[4];
            pa[0] = h2pack(sacc[2 * kf][0],     sacc[2 * kf][1]);
            pa[1] = h2pack(sacc[2 * kf][2],     sacc[2 * kf][3]);
            pa[2] = h2pack(sacc[2 * kf + 1][0], sacc[2 * kf + 1][1]);
            pa[3] = h2pack(sacc[2 * kf + 1][2], sacc[2 * kf + 1][3]);
#pragma unroll
            for (int np = 0; np < 8; np++) {
                uint32_t vb[4];
                ldsm_x4_t(vb, vbase + kf * (16 * KPITCH_B) + np * 32);
                mma_f16(oacc[2 * np],     pa, vb[0], vb[1]);
                mma_f16(oacc[2 * np + 1], pa, vb[2], vb[3]);
            }
        }
        // no trailing barrier: next iteration's top barrier closes this tile
    }

    // ---- Epilogue: quad-reduce row sums once, normalize, store ----
    lrow0 += __shfl_xor_sync(0xffffffffu, lrow0, 1);
    lrow0 += __shfl_xor_sync(0xffffffffu, lrow0, 2);
    lrow1 += __shfl_xor_sync(0xffffffffu, lrow1, 1);
    lrow1 += __shfl_xor_sync(0xffffffffu, lrow1, 2);
    float inv0 = 1.0f / lrow0;
    float inv1 = 1.0f / lrow1;
    float* o0 = out + ((size_t)bh * S_ + (m0 + rl0)) * D_;
    float* o1 = out + ((size_t)bh * S_ + (m0 + rl0 + 8)) * D_;
#pragma unroll
    for (int nf = 0; nf < 16; nf++) {
        int c = nf * 8 + 2 * t4;
        *(float2*)(o0 + c) = make_float2(oacc[nf][0] * inv0, oacc[nf][1] * inv0);
        *(float2*)(o1 + c) = make_float2(oacc[nf][2] * inv1, oacc[nf][3] * inv1);
    }
}

// ---------------------------------------------------------------------------
extern "C" void kernel_launch(void* const* d_in, const int* in_sizes, int n_in,
                              void* d_out, int out_size) {
    const float* q     = (const float*)d_in[0];
    const float* k     = (const float*)d_in[1];
    const float* v     = (const float*)d_in[2];
    const float* freqs = (const float*)d_in[3];
    float* out = (float*)d_out;
    (void)in_sizes; (void)n_in; (void)out_size;

    cudaFuncSetAttribute(attn_kernel,
                         cudaFuncAttributeMaxDynamicSharedMemorySize, SMEM_BYTES);

    const int TOTAL8 = B_ * S_ * H_ * (D_ / 8);   // 1,048,576 threads
    rope_prep_kernel<<<TOTAL8 / 256, 256>>>(q, k, v, freqs);

    dim3 grid(BH_, S_ / BM);
    attn_kernel<<<grid, NTHREADS, SMEM_BYTES>>>(out);
}

// round 10
// speedup vs baseline: 2.1628x; 1.0248x over previous
#include <cuda_runtime.h>
#include <cuda_fp16.h>
#include <cstdint>

// ---------------------------------------------------------------------------
// PatternCWanRoPE R10: fp16 warp-MMA flash attention (m16n8k16) + ldmatrix
//   + register P-pass + cp.async double-buffered K/V pipeline
//   + single barrier per tile
//   + QK loop nest swapped (accumulator RAW distance 2 -> 8 MMAs)
//   + row sums computed on tensor pipe via mma with all-ones B
//     (no shuffles / scalar sum adds; exact, consistent with PV numerator).
//   q,k,v : (B=2, S=2048, H=16, D=128) fp32   freqs : (1,S,1,D)
//   out   : (B,H,S,D) fp32
// ---------------------------------------------------------------------------

#define B_ 2
#define S_ 2048
#define H_ 16
#define D_ 128
#define BH_ 32

#define BM 64
#define BN 64
#define NTHREADS 128

#define KPITCH_B 272              // 136 halves/row (128 data + 8 pad); 17x16B
#define TILE_B   (64 * KPITCH_B)  // 17408 bytes per K or V tile
#define OFF_Q    0
#define OFF_B0   TILE_B           // buf0: K at +0, V at +TILE_B
#define OFF_B1   (OFF_B0 + 2 * TILE_B)
#define SMEM_BYTES (OFF_B1 + 2 * TILE_B)   // 87040

#define ONES_H2 0x3C003C00u       // half2(1.0, 1.0)

// fp16 scratch in (B,H,S,D): rope'd Q (pre-scaled by 1/sqrt(D)*log2e), K, V.
__device__ __half g_q[(size_t)BH_ * S_ * D_];
__device__ __half g_k[(size_t)BH_ * S_ * D_];
__device__ __half g_v[(size_t)BH_ * S_ * D_];

// ---------------------------------------------------------------------------
__device__ __forceinline__ uint32_t smem_u32(const void* p) {
    uint32_t a;
    asm("{ .reg .u64 t; cvta.to.shared.u64 t, %1; cvt.u32.u64 %0, t; }"
        : "=r"(a) : "l"(p));
    return a;
}
__device__ __forceinline__ float fast_exp2(float x) {
    float y; asm("ex2.approx.f32 %0, %1;" : "=f"(y) : "f"(x));
    return y;
}
__device__ __forceinline__ uint32_t h2pack(float a, float b) {
    __half2 h = __floats2half2_rn(a, b);
    return *reinterpret_cast<uint32_t*>(&h);
}
__device__ __forceinline__ void ldsm_x4(uint32_t r[4], uint32_t a) {
    asm volatile("ldmatrix.sync.aligned.m8n8.x4.shared.b16 {%0,%1,%2,%3}, [%4];"
                 : "=r"(r[0]), "=r"(r[1]), "=r"(r[2]), "=r"(r[3]) : "r"(a));
}
__device__ __forceinline__ void ldsm_x4_t(uint32_t r[4], uint32_t a) {
    asm volatile("ldmatrix.sync.aligned.m8n8.x4.trans.shared.b16 {%0,%1,%2,%3}, [%4];"
                 : "=r"(r[0]), "=r"(r[1]), "=r"(r[2]), "=r"(r[3]) : "r"(a));
}
__device__ __forceinline__ void mma_f16(float c[4], const uint32_t a[4],
                                        uint32_t b0, uint32_t b1) {
    asm volatile(
        "mma.sync.aligned.m16n8k16.row.col.f32.f16.f16.f32 "
        "{%0,%1,%2,%3}, {%4,%5,%6,%7}, {%8,%9}, {%0,%1,%2,%3};\n"
        : "+f"(c[0]), "+f"(c[1]), "+f"(c[2]), "+f"(c[3])
        : "r"(a[0]), "r"(a[1]), "r"(a[2]), "r"(a[3]), "r"(b0), "r"(b1));
}
#define CP_COMMIT() asm volatile("cp.async.commit_group;" ::: "memory")
#define CP_WAIT0()  asm volatile("cp.async.wait_group 0;" ::: "memory")

// Prefetch one 64x128 fp16 K tile + V tile into SMEM buffer (one group).
__device__ __forceinline__ void cp_tile(const __half* __restrict__ Kg,
                                        const __half* __restrict__ Vg,
                                        uint32_t kbuf, uint32_t vbuf,
                                        int n0, int tid) {
#pragma unroll
    for (int i = 0; i < 8; i++) {
        int idx = tid + i * 128;
        int r = idx >> 4, c = idx & 15;
        uint32_t d = (uint32_t)(r * KPITCH_B + c * 16);
        asm volatile("cp.async.cg.shared.global [%0], [%1], 16;"
                     :: "r"(kbuf + d), "l"(Kg + (size_t)(n0 + r) * D_ + c * 8));
        asm volatile("cp.async.cg.shared.global [%0], [%1], 16;"
                     :: "r"(vbuf + d), "l"(Vg + (size_t)(n0 + r) * D_ + c * 8));
    }
    CP_COMMIT();
}

// ---------------------------------------------------------------------------
// Prologue: RoPE(q,k) + scale, fp16 convert, (B,S,H,D)->(B,H,S,D). V too.
// 8 halves (4 interleaved pairs) per thread; fully vectorized.
// ---------------------------------------------------------------------------
__global__ void rope_prep_kernel(const float* __restrict__ q,
                                 const float* __restrict__ k,
                                 const float* __restrict__ v,
                                 const float* __restrict__ freqs) {
    int pid = blockIdx.x * blockDim.x + threadIdx.x;
    int d8 = pid & 15;               // 16 groups of 8 elements
    int h  = (pid >> 4) & (H_ - 1);
    int s  = (pid >> 8) & (S_ - 1);
    int b  = pid >> 19;

    size_t in_off  = ((((size_t)b * S_ + s) * H_ + h) * D_) + 8 * d8;
    size_t f_off   = (size_t)s * D_ + 8 * d8;
    size_t out_off = ((((size_t)b * H_ + h) * S_ + s) * D_) + 8 * d8;

    const float QS = 0.08838834764831845f * 1.4426950408889634f; // 1/sqrt(D)*log2e

    float4 f0 = *(const float4*)(freqs + f_off);
    float4 f1 = *(const float4*)(freqs + f_off + 4);
    float4 q0 = *(const float4*)(q + in_off);
    float4 q1 = *(const float4*)(q + in_off + 4);
    float4 k0 = *(const float4*)(k + in_off);
    float4 k1 = *(const float4*)(k + in_off + 4);
    float4 v0 = *(const float4*)(v + in_off);
    float4 v1 = *(const float4*)(v + in_off + 4);

    uint4 oq, ok, ov;
    oq.x = h2pack((f0.x * q0.x - f0.y * q0.y) * QS, (f0.y * q0.x + f0.x * q0.y) * QS);
    oq.y = h2pack((f0.z * q0.z - f0.w * q0.w) * QS, (f0.w * q0.z + f0.z * q0.w) * QS);
    oq.z = h2pack((f1.x * q1.x - f1.y * q1.y) * QS, (f1.y * q1.x + f1.x * q1.y) * QS);
    oq.w = h2pack((f1.z * q1.z - f1.w * q1.w) * QS, (f1.w * q1.z + f1.z * q1.w) * QS);
    ok.x = h2pack(f0.x * k0.x - f0.y * k0.y, f0.y * k0.x + f0.x * k0.y);
    ok.y = h2pack(f0.z * k0.z - f0.w * k0.w, f0.w * k0.z + f0.z * k0.w);
    ok.z = h2pack(f1.x * k1.x - f1.y * k1.y, f1.y * k1.x + f1.x * k1.y);
    ok.w = h2pack(f1.z * k1.z - f1.w * k1.w, f1.w * k1.z + f1.z * k1.w);
    ov.x = h2pack(v0.x, v0.y);
    ov.y = h2pack(v0.z, v0.w);
    ov.z = h2pack(v1.x, v1.y);
    ov.w = h2pack(v1.z, v1.w);

    *(uint4*)(g_q + out_off) = oq;
    *(uint4*)(g_k + out_off) = ok;
    *(uint4*)(g_v + out_off) = ov;
}

// ---------------------------------------------------------------------------
// Flash attention. grid = (bh, q-tile [reversed]). 4 warps; warp w owns
// q rows [16w, 16w+16). ONE __syncthreads per tile.
// ---------------------------------------------------------------------------
__global__ void __launch_bounds__(NTHREADS, 2)
attn_kernel(float* __restrict__ out) {
    extern __shared__ __align__(16) char smem[];
    const uint32_t sb = smem_u32(smem);

    const int bh = blockIdx.x;
    const int qt = (int)(gridDim.y - 1) - (int)blockIdx.y;  // long rows first
    const int m0 = qt * BM;
    const int tid  = threadIdx.x;
    const int warp = tid >> 5;
    const int lane = tid & 31;
    const int g  = lane >> 2;
    const int t4 = lane & 3;

    const __half* Qg = g_q + (size_t)bh * S_ * D_;
    const __half* Kg = g_k + (size_t)bh * S_ * D_;
    const __half* Vg = g_v + (size_t)bh * S_ * D_;

    // Kick off tile 0 prefetch immediately (overlaps Q staging below).
    cp_tile(Kg, Vg, sb + OFF_B0, sb + OFF_B0 + TILE_B, 0, tid);

    // ---- Stage Q tile (64 x 128) at OFF_Q, then load fragments ----
#pragma unroll
    for (int i = 0; i < 8; i++) {
        int idx = tid + i * 128;
        int r = idx >> 4, c = idx & 15;
        uint4 x = *(const uint4*)(Qg + (size_t)(m0 + r) * D_ + c * 8);
        *(uint4*)(smem + OFF_Q + r * KPITCH_B + c * 16) = x;
    }
    __syncthreads();   // Q visible to all warps

    const uint32_t qaddr = sb + OFF_Q + (warp * 16 + (lane & 15)) * KPITCH_B
                         + (lane >> 4) * 16;
    uint32_t qa[8][4];
#pragma unroll
    for (int kf = 0; kf < 8; kf++) ldsm_x4(qa[kf], qaddr + kf * 32);

    // per-thread ldmatrix lane offsets (within a K / V tile)
    const uint32_t koff = ((lane >> 4) * 8 + (lane & 7)) * KPITCH_B
                        + ((lane >> 3) & 1) * 16;
    const uint32_t voff = (((lane >> 3) & 1) * 8 + (lane & 7)) * KPITCH_B
                        + (lane >> 4) * 16;

    float oacc[16][4];
#pragma unroll
    for (int i = 0; i < 16; i++) {
        oacc[i][0] = 0.f; oacc[i][1] = 0.f; oacc[i][2] = 0.f; oacc[i][3] = 0.f;
    }
    float sumacc[4] = {0.f, 0.f, 0.f, 0.f};   // row sums via mma-with-ones
    const int rl0 = warp * 16 + g;
    float mrow0 = -1e30f, mrow1 = -1e30f;     // running row max (log2 space)

    const int ntiles = qt + 1;
    for (int t = 0; t < ntiles; t++) {
        const uint32_t bufo = (t & 1) ? OFF_B1 : OFF_B0;

        // ---- Single barrier point per tile ----
        CP_WAIT0();
        __syncthreads();
        if (t + 1 < ntiles) {
            const uint32_t nb = ((t + 1) & 1) ? OFF_B1 : OFF_B0;
            cp_tile(Kg, Vg, sb + nb, sb + nb + TILE_B, (t + 1) * BN, tid);
        }

        const uint32_t kbase = sb + bufo + koff;
        const uint32_t vbase = sb + bufo + TILE_B + voff;

        // ---- S = Q K^T : kf OUTER so each sacc's RAW distance is 8 MMAs ----
        float sacc[8][4];
#pragma unroll
        for (int i = 0; i < 8; i++) {
            sacc[i][0] = 0.f; sacc[i][1] = 0.f; sacc[i][2] = 0.f; sacc[i][3] = 0.f;
        }
#pragma unroll
        for (int kf = 0; kf < 8; kf++) {
#pragma unroll
            for (int np = 0; np < 4; np++) {
                uint32_t b[4];
                ldsm_x4(b, kbase + np * (16 * KPITCH_B) + kf * 32);
                mma_f16(sacc[2 * np],     qa[kf], b[0], b[1]);
                mma_f16(sacc[2 * np + 1], qa[kf], b[2], b[3]);
            }
        }

        // ---- Causal mask (diagonal tile only) ----
        if (t == qt) {
#pragma unroll
            for (int nf = 0; nf < 8; nf++) {
                int c0 = nf * 8 + 2 * t4;
                if (c0     > rl0)     sacc[nf][0] = -1e30f;
                if (c0 + 1 > rl0)     sacc[nf][1] = -1e30f;
                if (c0     > rl0 + 8) sacc[nf][2] = -1e30f;
                if (c0 + 1 > rl0 + 8) sacc[nf][3] = -1e30f;
            }
        }

        // ---- Online softmax: row max via quad shuffle ----
        float tm0 = -1e30f, tm1 = -1e30f;
#pragma unroll
        for (int nf = 0; nf < 8; nf++) {
            tm0 = fmaxf(tm0, fmaxf(sacc[nf][0], sacc[nf][1]));
            tm1 = fmaxf(tm1, fmaxf(sacc[nf][2], sacc[nf][3]));
        }
        tm0 = fmaxf(tm0, __shfl_xor_sync(0xffffffffu, tm0, 1));
        tm0 = fmaxf(tm0, __shfl_xor_sync(0xffffffffu, tm0, 2));
        tm1 = fmaxf(tm1, __shfl_xor_sync(0xffffffffu, tm1, 1));
        tm1 = fmaxf(tm1, __shfl_xor_sync(0xffffffffu, tm1, 2));

        // Alpha-skip: rescale O / sums only when the running max increases.
        if (tm0 > mrow0 || tm1 > mrow1) {
            float mn0 = fmaxf(mrow0, tm0);
            float mn1 = fmaxf(mrow1, tm1);
            float alpha0 = fast_exp2(mrow0 - mn0);
            float alpha1 = fast_exp2(mrow1 - mn1);
            mrow0 = mn0; mrow1 = mn1;
            sumacc[0] *= alpha0; sumacc[2] *= alpha1;
#pragma unroll
            for (int nf = 0; nf < 16; nf++) {
                oacc[nf][0] *= alpha0; oacc[nf][1] *= alpha0;
                oacc[nf][2] *= alpha1; oacc[nf][3] *= alpha1;
            }
        }

        // ---- P = exp2(S - m), packed straight into A fragments ----
        uint32_t paf[4][4];
#pragma unroll
        for (int nf = 0; nf < 8; nf++) {
            sacc[nf][0] = fast_exp2(sacc[nf][0] - mrow0);
            sacc[nf][1] = fast_exp2(sacc[nf][1] - mrow0);
            sacc[nf][2] = fast_exp2(sacc[nf][2] - mrow1);
            sacc[nf][3] = fast_exp2(sacc[nf][3] - mrow1);
        }
#pragma unroll
        for (int kf = 0; kf < 4; kf++) {
            paf[kf][0] = h2pack(sacc[2 * kf][0],     sacc[2 * kf][1]);
            paf[kf][1] = h2pack(sacc[2 * kf][2],     sacc[2 * kf][3]);
            paf[kf][2] = h2pack(sacc[2 * kf + 1][0], sacc[2 * kf + 1][1]);
            paf[kf][3] = h2pack(sacc[2 * kf + 1][2], sacc[2 * kf + 1][3]);
        }

        // ---- Row sums on the tensor pipe: every column of P*ones is the
        //      row sum -> sumacc[0] = sum(row rl0), sumacc[2] = sum(rl0+8). ----
#pragma unroll
        for (int kf = 0; kf < 4; kf++)
            mma_f16(sumacc, paf[kf], ONES_H2, ONES_H2);

        // ---- O += P V ----
#pragma unroll
        for (int kf = 0; kf < 4; kf++) {
#pragma unroll
            for (int np = 0; np < 8; np++) {
                uint32_t vb[4];
                ldsm_x4_t(vb, vbase + kf * (16 * KPITCH_B) + np * 32);
                mma_f16(oacc[2 * np],     paf[kf], vb[0], vb[1]);
                mma_f16(oacc[2 * np + 1], paf[kf], vb[2], vb[3]);
            }
        }
        // no trailing barrier: next iteration's top barrier closes this tile
    }

    // ---- Epilogue: normalize and store (B,H,S,D); sums already complete ----
    float inv0 = 1.0f / sumacc[0];
    float inv1 = 1.0f / sumacc[2];
    float* o0 = out + ((size_t)bh * S_ + (m0 + rl0)) * D_;
    float* o1 = out + ((size_t)bh * S_ + (m0 + rl0 + 8)) * D_;
#pragma unroll
    for (int nf = 0; nf < 16; nf++) {
        int c = nf * 8 + 2 * t4;
        *(float2*)(o0 + c) = make_float2(oacc[nf][0] * inv0, oacc[nf][1] * inv0);
        *(float2*)(o1 + c) = make_float2(oacc[nf][2] * inv1, oacc[nf][3] * inv1);
    }
}

// ---------------------------------------------------------------------------
extern "C" void kernel_launch(void* const* d_in, const int* in_sizes, int n_in,
                              void* d_out, int out_size) {
    const float* q     = (const float*)d_in[0];
    const float* k     = (const float*)d_in[1];
    const float* v     = (const float*)d_in[2];
    const float* freqs = (const float*)d_in[3];
    float* out = (float*)d_out;
    (void)in_sizes; (void)n_in; (void)out_size;

    cudaFuncSetAttribute(attn_kernel,
                         cudaFuncAttributeMaxDynamicSharedMemorySize, SMEM_BYTES);

    const int TOTAL8 = B_ * S_ * H_ * (D_ / 8);   // 1,048,576 threads
    rope_prep_kernel<<<TOTAL8 / 256, 256>>>(q, k, v, freqs);

    dim3 grid(BH_, S_ / BM);
    attn_kernel<<<grid, NTHREADS, SMEM_BYTES>>>(out);
}

// round 11
// speedup vs baseline: 2.2026x; 1.0184x over previous
#include <cuda_runtime.h>
#include <cuda_fp16.h>
#include <cstdint>

// ---------------------------------------------------------------------------
// PatternCWanRoPE R11: fp16 warp-MMA flash attention (m16n8k16) + ldmatrix
//   + register P-pass + cp.async double-buffered K/V pipeline
//   + single barrier per tile, QK kf-outer (RAW distance 8)
//   + exp2 via ex2.approx.f16x2 fused into P-fragment packing
//   + row sums on tensor pipe with TWO interleaved accumulators
//   + streaming (__ldcs) prologue reads to keep L2 for fp16 scratch.
//   q,k,v : (B=2, S=2048, H=16, D=128) fp32   freqs : (1,S,1,D)
//   out   : (B,H,S,D) fp32
// ---------------------------------------------------------------------------

#define B_ 2
#define S_ 2048
#define H_ 16
#define D_ 128
#define BH_ 32

#define BM 64
#define BN 64
#define NTHREADS 128

#define KPITCH_B 272              // 136 halves/row (128 data + 8 pad); 17x16B
#define TILE_B   (64 * KPITCH_B)  // 17408 bytes per K or V tile
#define OFF_Q    0
#define OFF_B0   TILE_B           // buf0: K at +0, V at +TILE_B
#define OFF_B1   (OFF_B0 + 2 * TILE_B)
#define SMEM_BYTES (OFF_B1 + 2 * TILE_B)   // 87040

#define ONES_H2 0x3C003C00u       // half2(1.0, 1.0)

// fp16 scratch in (B,H,S,D): rope'd Q (pre-scaled by 1/sqrt(D)*log2e), K, V.
__device__ __half g_q[(size_t)BH_ * S_ * D_];
__device__ __half g_k[(size_t)BH_ * S_ * D_];
__device__ __half g_v[(size_t)BH_ * S_ * D_];

// ---------------------------------------------------------------------------
__device__ __forceinline__ uint32_t smem_u32(const void* p) {
    uint32_t a;
    asm("{ .reg .u64 t; cvta.to.shared.u64 t, %1; cvt.u32.u64 %0, t; }"
        : "=r"(a) : "l"(p));
    return a;
}
__device__ __forceinline__ float fast_exp2(float x) {
    float y; asm("ex2.approx.f32 %0, %1;" : "=f"(y) : "f"(x));
    return y;
}
__device__ __forceinline__ uint32_t ex2_h2(uint32_t x) {
    uint32_t y; asm("ex2.approx.f16x2 %0, %1;" : "=r"(y) : "r"(x));
    return y;
}
__device__ __forceinline__ uint32_t h2pack(float a, float b) {
    __half2 h = __floats2half2_rn(a, b);
    return *reinterpret_cast<uint32_t*>(&h);
}
__device__ __forceinline__ void ldsm_x4(uint32_t r[4], uint32_t a) {
    asm volatile("ldmatrix.sync.aligned.m8n8.x4.shared.b16 {%0,%1,%2,%3}, [%4];"
                 : "=r"(r[0]), "=r"(r[1]), "=r"(r[2]), "=r"(r[3]) : "r"(a));
}
__device__ __forceinline__ void ldsm_x4_t(uint32_t r[4], uint32_t a) {
    asm volatile("ldmatrix.sync.aligned.m8n8.x4.trans.shared.b16 {%0,%1,%2,%3}, [%4];"
                 : "=r"(r[0]), "=r"(r[1]), "=r"(r[2]), "=r"(r[3]) : "r"(a));
}
__device__ __forceinline__ void mma_f16(float c[4], const uint32_t a[4],
                                        uint32_t b0, uint32_t b1) {
    asm volatile(
        "mma.sync.aligned.m16n8k16.row.col.f32.f16.f16.f32 "
        "{%0,%1,%2,%3}, {%4,%5,%6,%7}, {%8,%9}, {%0,%1,%2,%3};\n"
        : "+f"(c[0]), "+f"(c[1]), "+f"(c[2]), "+f"(c[3])
        : "r"(a[0]), "r"(a[1]), "r"(a[2]), "r"(a[3]), "r"(b0), "r"(b1));
}
#define CP_COMMIT() asm volatile("cp.async.commit_group;" ::: "memory")
#define CP_WAIT0()  asm volatile("cp.async.wait_group 0;" ::: "memory")

// Prefetch one 64x128 fp16 K tile + V tile into SMEM buffer (one group).
__device__ __forceinline__ void cp_tile(const __half* __restrict__ Kg,
                                        const __half* __restrict__ Vg,
                                        uint32_t kbuf, uint32_t vbuf,
                                        int n0, int tid) {
#pragma unroll
    for (int i = 0; i < 8; i++) {
        int idx = tid + i * 128;
        int r = idx >> 4, c = idx & 15;
        uint32_t d = (uint32_t)(r * KPITCH_B + c * 16);
        asm volatile("cp.async.cg.shared.global [%0], [%1], 16;"
                     :: "r"(kbuf + d), "l"(Kg + (size_t)(n0 + r) * D_ + c * 8));
        asm volatile("cp.async.cg.shared.global [%0], [%1], 16;"
                     :: "r"(vbuf + d), "l"(Vg + (size_t)(n0 + r) * D_ + c * 8));
    }
    CP_COMMIT();
}

// ---------------------------------------------------------------------------
// Prologue: RoPE(q,k) + scale, fp16 convert, (B,S,H,D)->(B,H,S,D). V too.
// 8 halves (4 interleaved pairs) per thread; streaming loads.
// ---------------------------------------------------------------------------
__global__ void rope_prep_kernel(const float* __restrict__ q,
                                 const float* __restrict__ k,
                                 const float* __restrict__ v,
                                 const float* __restrict__ freqs) {
    int pid = blockIdx.x * blockDim.x + threadIdx.x;
    int d8 = pid & 15;               // 16 groups of 8 elements
    int h  = (pid >> 4) & (H_ - 1);
    int s  = (pid >> 8) & (S_ - 1);
    int b  = pid >> 19;

    size_t in_off  = ((((size_t)b * S_ + s) * H_ + h) * D_) + 8 * d8;
    size_t f_off   = (size_t)s * D_ + 8 * d8;
    size_t out_off = ((((size_t)b * H_ + h) * S_ + s) * D_) + 8 * d8;

    const float QS = 0.08838834764831845f * 1.4426950408889634f; // 1/sqrt(D)*log2e

    float4 f0 = *(const float4*)(freqs + f_off);
    float4 f1 = *(const float4*)(freqs + f_off + 4);
    float4 q0 = __ldcs((const float4*)(q + in_off));
    float4 q1 = __ldcs((const float4*)(q + in_off + 4));
    float4 k0 = __ldcs((const float4*)(k + in_off));
    float4 k1 = __ldcs((const float4*)(k + in_off + 4));
    float4 v0 = __ldcs((const float4*)(v + in_off));
    float4 v1 = __ldcs((const float4*)(v + in_off + 4));

    uint4 oq, ok, ov;
    oq.x = h2pack((f0.x * q0.x - f0.y * q0.y) * QS, (f0.y * q0.x + f0.x * q0.y) * QS);
    oq.y = h2pack((f0.z * q0.z - f0.w * q0.w) * QS, (f0.w * q0.z + f0.z * q0.w) * QS);
    oq.z = h2pack((f1.x * q1.x - f1.y * q1.y) * QS, (f1.y * q1.x + f1.x * q1.y) * QS);
    oq.w = h2pack((f1.z * q1.z - f1.w * q1.w) * QS, (f1.w * q1.z + f1.z * q1.w) * QS);
    ok.x = h2pack(f0.x * k0.x - f0.y * k0.y, f0.y * k0.x + f0.x * k0.y);
    ok.y = h2pack(f0.z * k0.z - f0.w * k0.w, f0.w * k0.z + f0.z * k0.w);
    ok.z = h2pack(f1.x * k1.x - f1.y * k1.y, f1.y * k1.x + f1.x * k1.y);
    ok.w = h2pack(f1.z * k1.z - f1.w * k1.w, f1.w * k1.z + f1.z * k1.w);
    ov.x = h2pack(v0.x, v0.y);
    ov.y = h2pack(v0.z, v0.w);
    ov.z = h2pack(v1.x, v1.y);
    ov.w = h2pack(v1.z, v1.w);

    *(uint4*)(g_q + out_off) = oq;
    *(uint4*)(g_k + out_off) = ok;
    *(uint4*)(g_v + out_off) = ov;
}

// ---------------------------------------------------------------------------
// Flash attention. grid = (bh, q-tile [reversed]). 4 warps; warp w owns
// q rows [16w, 16w+16). ONE __syncthreads per tile.
// ---------------------------------------------------------------------------
__global__ void __launch_bounds__(NTHREADS, 2)
attn_kernel(float* __restrict__ out) {
    extern __shared__ __align__(16) char smem[];
    const uint32_t sb = smem_u32(smem);

    const int bh = blockIdx.x;
    const int qt = (int)(gridDim.y - 1) - (int)blockIdx.y;  // long rows first
    const int m0 = qt * BM;
    const int tid  = threadIdx.x;
    const int warp = tid >> 5;
    const int lane = tid & 31;
    const int g  = lane >> 2;
    const int t4 = lane & 3;

    const __half* Qg = g_q + (size_t)bh * S_ * D_;
    const __half* Kg = g_k + (size_t)bh * S_ * D_;
    const __half* Vg = g_v + (size_t)bh * S_ * D_;

    // Kick off tile 0 prefetch immediately (overlaps Q staging below).
    cp_tile(Kg, Vg, sb + OFF_B0, sb + OFF_B0 + TILE_B, 0, tid);

    // ---- Stage Q tile (64 x 128) at OFF_Q, then load fragments ----
#pragma unroll
    for (int i = 0; i < 8; i++) {
        int idx = tid + i * 128;
        int r = idx >> 4, c = idx & 15;
        uint4 x = *(const uint4*)(Qg + (size_t)(m0 + r) * D_ + c * 8);
        *(uint4*)(smem + OFF_Q + r * KPITCH_B + c * 16) = x;
    }
    __syncthreads();   // Q visible to all warps

    const uint32_t qaddr = sb + OFF_Q + (warp * 16 + (lane & 15)) * KPITCH_B
                         + (lane >> 4) * 16;
    uint32_t qa[8][4];
#pragma unroll
    for (int kf = 0; kf < 8; kf++) ldsm_x4(qa[kf], qaddr + kf * 32);

    // per-thread ldmatrix lane offsets (within a K / V tile)
    const uint32_t koff = ((lane >> 4) * 8 + (lane & 7)) * KPITCH_B
                        + ((lane >> 3) & 1) * 16;
    const uint32_t voff = (((lane >> 3) & 1) * 8 + (lane & 7)) * KPITCH_B
                        + (lane >> 4) * 16;

    float oacc[16][4];
#pragma unroll
    for (int i = 0; i < 16; i++) {
        oacc[i][0] = 0.f; oacc[i][1] = 0.f; oacc[i][2] = 0.f; oacc[i][3] = 0.f;
    }
    float sumA[4] = {0.f, 0.f, 0.f, 0.f};   // row sums via mma-with-ones
    float sumB[4] = {0.f, 0.f, 0.f, 0.f};   // (two accumulators: RAW dist 2)
    const int rl0 = warp * 16 + g;
    float mrow0 = -1e30f, mrow1 = -1e30f;   // running row max (log2 space)

    const int ntiles = qt + 1;
    for (int t = 0; t < ntiles; t++) {
        const uint32_t bufo = (t & 1) ? OFF_B1 : OFF_B0;

        // ---- Single barrier point per tile ----
        CP_WAIT0();
        __syncthreads();
        if (t + 1 < ntiles) {
            const uint32_t nb = ((t + 1) & 1) ? OFF_B1 : OFF_B0;
            cp_tile(Kg, Vg, sb + nb, sb + nb + TILE_B, (t + 1) * BN, tid);
        }

        const uint32_t kbase = sb + bufo + koff;
        const uint32_t vbase = sb + bufo + TILE_B + voff;

        // ---- S = Q K^T : kf OUTER so each sacc's RAW distance is 8 MMAs ----
        float sacc[8][4];
#pragma unroll
        for (int i = 0; i < 8; i++) {
            sacc[i][0] = 0.f; sacc[i][1] = 0.f; sacc[i][2] = 0.f; sacc[i][3] = 0.f;
        }
#pragma unroll
        for (int kf = 0; kf < 8; kf++) {
#pragma unroll
            for (int np = 0; np < 4; np++) {
                uint32_t b[4];
                ldsm_x4(b, kbase + np * (16 * KPITCH_B) + kf * 32);
                mma_f16(sacc[2 * np],     qa[kf], b[0], b[1]);
                mma_f16(sacc[2 * np + 1], qa[kf], b[2], b[3]);
            }
        }

        // ---- Causal mask (diagonal tile only) ----
        if (t == qt) {
#pragma unroll
            for (int nf = 0; nf < 8; nf++) {
                int c0 = nf * 8 + 2 * t4;
                if (c0     > rl0)     sacc[nf][0] = -1e30f;
                if (c0 + 1 > rl0)     sacc[nf][1] = -1e30f;
                if (c0     > rl0 + 8) sacc[nf][2] = -1e30f;
                if (c0 + 1 > rl0 + 8) sacc[nf][3] = -1e30f;
            }
        }

        // ---- Online softmax: row max via quad shuffle ----
        float tm0 = -1e30f, tm1 = -1e30f;
#pragma unroll
        for (int nf = 0; nf < 8; nf++) {
            tm0 = fmaxf(tm0, fmaxf(sacc[nf][0], sacc[nf][1]));
            tm1 = fmaxf(tm1, fmaxf(sacc[nf][2], sacc[nf][3]));
        }
        tm0 = fmaxf(tm0, __shfl_xor_sync(0xffffffffu, tm0, 1));
        tm0 = fmaxf(tm0, __shfl_xor_sync(0xffffffffu, tm0, 2));
        tm1 = fmaxf(tm1, __shfl_xor_sync(0xffffffffu, tm1, 1));
        tm1 = fmaxf(tm1, __shfl_xor_sync(0xffffffffu, tm1, 2));

        // Alpha-skip: rescale O / sums only when the running max increases.
        if (tm0 > mrow0 || tm1 > mrow1) {
            float mn0 = fmaxf(mrow0, tm0);
            float mn1 = fmaxf(mrow1, tm1);
            float alpha0 = fast_exp2(mrow0 - mn0);
            float alpha1 = fast_exp2(mrow1 - mn1);
            mrow0 = mn0; mrow1 = mn1;
            sumA[0] *= alpha0; sumA[2] *= alpha1;
            sumB[0] *= alpha0; sumB[2] *= alpha1;
#pragma unroll
            for (int nf = 0; nf < 16; nf++) {
                oacc[nf][0] *= alpha0; oacc[nf][1] *= alpha0;
                oacc[nf][2] *= alpha1; oacc[nf][3] *= alpha1;
            }
        }

        // ---- P = exp2(S - m): fp32 subtract, pack to half2, one MUFU per
        //      pair (ex2.approx.f16x2). Output IS the PV A-fragment. ----
        uint32_t paf[4][4];
#pragma unroll
        for (int kf = 0; kf < 4; kf++) {
            paf[kf][0] = ex2_h2(h2pack(sacc[2 * kf][0] - mrow0,
                                       sacc[2 * kf][1] - mrow0));
            paf[kf][1] = ex2_h2(h2pack(sacc[2 * kf][2] - mrow1,
                                       sacc[2 * kf][3] - mrow1));
            paf[kf][2] = ex2_h2(h2pack(sacc[2 * kf + 1][0] - mrow0,
                                       sacc[2 * kf + 1][1] - mrow0));
            paf[kf][3] = ex2_h2(h2pack(sacc[2 * kf + 1][2] - mrow1,
                                       sacc[2 * kf + 1][3] - mrow1));
        }

        // ---- Row sums on the tensor pipe (interleaved accumulators):
        //      every column of P*ones is the row sum. ----
        mma_f16(sumA, paf[0], ONES_H2, ONES_H2);
        mma_f16(sumB, paf[1], ONES_H2, ONES_H2);
        mma_f16(sumA, paf[2], ONES_H2, ONES_H2);
        mma_f16(sumB, paf[3], ONES_H2, ONES_H2);

        // ---- O += P V ----
#pragma unroll
        for (int kf = 0; kf < 4; kf++) {
#pragma unroll
            for (int np = 0; np < 8; np++) {
                uint32_t vb[4];
                ldsm_x4_t(vb, vbase + kf * (16 * KPITCH_B) + np * 32);
                mma_f16(oacc[2 * np],     paf[kf], vb[0], vb[1]);
                mma_f16(oacc[2 * np + 1], paf[kf], vb[2], vb[3]);
            }
        }
        // no trailing barrier: next iteration's top barrier closes this tile
    }

    // ---- Epilogue: normalize and store (B,H,S,D); sums already complete ----
    float inv0 = 1.0f / (sumA[0] + sumB[0]);
    float inv1 = 1.0f / (sumA[2] + sumB[2]);
    float* o0 = out + ((size_t)bh * S_ + (m0 + rl0)) * D_;
    float* o1 = out + ((size_t)bh * S_ + (m0 + rl0 + 8)) * D_;
#pragma unroll
    for (int nf = 0; nf < 16; nf++) {
        int c = nf * 8 + 2 * t4;
        *(float2*)(o0 + c) = make_float2(oacc[nf][0] * inv0, oacc[nf][1] * inv0);
        *(float2*)(o1 + c) = make_float2(oacc[nf][2] * inv1, oacc[nf][3] * inv1);
    }
}

// ---------------------------------------------------------------------------
extern "C" void kernel_launch(void* const* d_in, const int* in_sizes, int n_in,
                              void* d_out, int out_size) {
    const float* q     = (const float*)d_in[0];
    const float* k     = (const float*)d_in[1];
    const float* v     = (const float*)d_in[2];
    const float* freqs = (const float*)d_in[3];
    float* out = (float*)d_out;
    (void)in_sizes; (void)n_in; (void)out_size;

    cudaFuncSetAttribute(attn_kernel,
                         cudaFuncAttributeMaxDynamicSharedMemorySize, SMEM_BYTES);

    const int TOTAL8 = B_ * S_ * H_ * (D_ / 8);   // 1,048,576 threads
    rope_prep_kernel<<<TOTAL8 / 256, 256>>>(q, k, v, freqs);

    dim3 grid(BH_, S_ / BM);
    attn_kernel<<<grid, NTHREADS, SMEM_BYTES>>>(out);
}